// round 8
// baseline (speedup 1.0000x reference)
#include <cuda_runtime.h>
#include <cuda_bf16.h>
#include <cstdint>
#include <cstddef>

// Problem constants
static constexpr int Bn = 4;
static constexpr int Sn = 2048;
static constexpr int En = 1024;
static constexpr int Hn = 16;
static constexpr int Dn = 64;

// Scratch (device globals; no cudaMalloc allowed)
__device__ float g_qkv[(size_t)Bn * Sn * 3 * En];   // [B,S,3E]
__device__ float g_attn[(size_t)Bn * Sn * En];      // [B,S,E]

__device__ __forceinline__ float tf32_rna(float x) {
    uint32_t u;
    asm("cvt.rna.tf32.f32 %0, %1;" : "=r"(u) : "f"(x));
    return __uint_as_float(u);
}

// Warp-level tf32 MMA (attention): D(16x8) += A(16x8) * B(8x8), fp32 acc.
__device__ __forceinline__ void mma_tf32(float* c, const uint32_t* a, const uint32_t* b) {
    asm volatile(
        "mma.sync.aligned.m16n8k8.row.col.f32.tf32.tf32.f32 "
        "{%0,%1,%2,%3}, {%4,%5,%6,%7}, {%8,%9}, {%0,%1,%2,%3};"
        : "+f"(c[0]), "+f"(c[1]), "+f"(c[2]), "+f"(c[3])
        : "r"(a[0]), "r"(a[1]), "r"(a[2]), "r"(a[3]), "r"(b[0]), "r"(b[1]));
}

// Warp-level bf16 MMA: D(16x8) += A(16x16) * B(16x8), fp32 acc.
__device__ __forceinline__ void mma_bf16(float* c, const uint32_t* a, const uint32_t* b) {
    asm volatile(
        "mma.sync.aligned.m16n8k16.row.col.f32.bf16.bf16.f32 "
        "{%0,%1,%2,%3}, {%4,%5,%6,%7}, {%8,%9}, {%0,%1,%2,%3};"
        : "+f"(c[0]), "+f"(c[1]), "+f"(c[2]), "+f"(c[3])
        : "r"(a[0]), "r"(a[1]), "r"(a[2]), "r"(a[3]), "r"(b[0]), "r"(b[1]));
}

// Split x into bf16 hi + lo, packing pairs (x0 -> low half, x1 -> high half).
__device__ __forceinline__ void split_pack_bf16(float x0, float x1,
                                                uint32_t& hi, uint32_t& lo) {
    __nv_bfloat162 h = __floats2bfloat162_rn(x0, x1);
    float f0 = __bfloat162float(h.x);
    float f1 = __bfloat162float(h.y);
    __nv_bfloat162 l = __floats2bfloat162_rn(x0 - f0, x1 - f1);
    hi = *(uint32_t*)&h;
    lo = *(uint32_t*)&l;
}

// ============================================================================
// 3xBF16 tensor-core GEMM (R7 proven): C = A @ Bw^T + bias
// ============================================================================
static constexpr int GBM = 128, GBN = 128, GBK = 32;
static constexpr int STAGE_E = 16384;                // bf16 elems per stage
static constexpr int GEMM_SMEM = 2 * STAGE_E * 2;    // 65536 bytes

__global__ __launch_bounds__(256, 2) void gemm_mma_bf16(
    const float* __restrict__ A, const float* __restrict__ Bw,
    const float* __restrict__ bias, float* __restrict__ C,
    int M, int N, int K)
{
    extern __shared__ uint16_t smu[];
    uint32_t* sm32 = (uint32_t*)smu;

    const int tid = threadIdx.x;
    const int wid = tid >> 5;
    const int lane = tid & 31;
    const int g = lane >> 2;
    const int t4 = lane & 3;
    const int wm = wid >> 1;
    const int wn = wid & 1;
    const int bm = blockIdx.y * GBM;
    const int bn = blockIdx.x * GBN;
    const int kT = K / GBK;

    float acc[2][8][4];
#pragma unroll
    for (int mt = 0; mt < 2; mt++)
#pragma unroll
        for (int nt = 0; nt < 8; nt++)
#pragma unroll
            for (int i = 0; i < 4; i++) acc[mt][nt][i] = 0.f;

    const int lrow = tid >> 3;
    const int lq = tid & 7;
    const int k0l = lq * 4;
    const int kblkL = k0l >> 4;
    const int kcL = k0l & 15;
    const int khalfL = kcL >> 3;
    const int t4L = (kcL & 7) >> 1;

    int aw[4], bw2[4];
#pragma unroll
    for (int s = 0; s < 4; s++) {
        const int row = lrow + s * 32;
        const int mblk = row >> 4, r16 = row & 15;
        const int halfA = r16 >> 3, gA = r16 & 7;
        const int aoff = (mblk * 2 + kblkL) * 256 + gA * 32 + khalfL * 4 + halfA * 2;
        aw[s] = (aoff >> 1) + t4L * 4;
        const int nblk = row >> 3, gB = row & 7;
        const int boff = (nblk * 2 + kblkL) * 128 + gB * 16 + khalfL * 2;
        bw2[s] = (boff >> 1) + t4L * 2;
    }

    float4 pa[4], pb[4];
#pragma unroll
    for (int s = 0; s < 4; s++) {
        const int row = lrow + s * 32;
        pa[s] = *(const float4*)(A + (size_t)(bm + row) * K + k0l);
        pb[s] = *(const float4*)(Bw + (size_t)(bn + row) * K + k0l);
    }

    {
        uint32_t* AH = sm32;
        uint32_t* AL = sm32 + 2048;
        uint32_t* BH = sm32 + 4096;
        uint32_t* BL = sm32 + 6144;
#pragma unroll
        for (int s = 0; s < 4; s++) {
            uint32_t h01, l01, h23, l23;
            split_pack_bf16(pa[s].x, pa[s].y, h01, l01);
            split_pack_bf16(pa[s].z, pa[s].w, h23, l23);
            AH[aw[s]] = h01; AH[aw[s] + 4] = h23;
            AL[aw[s]] = l01; AL[aw[s] + 4] = l23;
            split_pack_bf16(pb[s].x, pb[s].y, h01, l01);
            split_pack_bf16(pb[s].z, pb[s].w, h23, l23);
            BH[bw2[s]] = h01; BH[bw2[s] + 2] = h23;
            BL[bw2[s]] = l01; BL[bw2[s] + 2] = l23;
        }
    }
    __syncthreads();

    for (int j = 0; j < kT; j++) {
        const int st = j & 1;
        if (j + 1 < kT) {
            const int k0 = (j + 1) * GBK + k0l;
#pragma unroll
            for (int s = 0; s < 4; s++) {
                const int row = lrow + s * 32;
                pa[s] = *(const float4*)(A + (size_t)(bm + row) * K + k0);
                pb[s] = *(const float4*)(Bw + (size_t)(bn + row) * K + k0);
            }
        }

        const uint16_t* stg = smu + st * STAGE_E;
#pragma unroll
        for (int kblk = 0; kblk < 2; kblk++) {
            uint4 ahi[2], alo[2];
#pragma unroll
            for (int mt = 0; mt < 2; mt++) {
                const int mblk = wm * 2 + mt;
                const int base = (mblk * 2 + kblk) * 256 + g * 32 + t4 * 8;
                ahi[mt] = *(const uint4*)(stg + base);
                alo[mt] = *(const uint4*)(stg + 4096 + base);
            }
#pragma unroll
            for (int nt = 0; nt < 8; nt++) {
                const int nblk = wn * 8 + nt;
                const int bbase = (nblk * 2 + kblk) * 128 + g * 16 + t4 * 4;
                uint2 bh = *(const uint2*)(stg + 8192 + bbase);
                uint2 bl = *(const uint2*)(stg + 12288 + bbase);
#pragma unroll
                for (int mt = 0; mt < 2; mt++) {
                    mma_bf16(acc[mt][nt], (const uint32_t*)&ahi[mt], (const uint32_t*)&bh);
                    mma_bf16(acc[mt][nt], (const uint32_t*)&ahi[mt], (const uint32_t*)&bl);
                    mma_bf16(acc[mt][nt], (const uint32_t*)&alo[mt], (const uint32_t*)&bh);
                }
            }
        }

        if (j + 1 < kT) {
            const int so = st ^ 1;
            uint32_t* AH = sm32 + so * (STAGE_E / 2);
            uint32_t* AL = AH + 2048;
            uint32_t* BH = AH + 4096;
            uint32_t* BL = AH + 6144;
#pragma unroll
            for (int s = 0; s < 4; s++) {
                uint32_t h01, l01, h23, l23;
                split_pack_bf16(pa[s].x, pa[s].y, h01, l01);
                split_pack_bf16(pa[s].z, pa[s].w, h23, l23);
                AH[aw[s]] = h01; AH[aw[s] + 4] = h23;
                AL[aw[s]] = l01; AL[aw[s] + 4] = l23;
                split_pack_bf16(pb[s].x, pb[s].y, h01, l01);
                split_pack_bf16(pb[s].z, pb[s].w, h23, l23);
                BH[bw2[s]] = h01; BH[bw2[s] + 2] = h23;
                BL[bw2[s]] = l01; BL[bw2[s] + 2] = l23;
            }
        }
        __syncthreads();
    }

#pragma unroll
    for (int mt = 0; mt < 2; mt++) {
        const int r0 = bm + wm * 32 + mt * 16 + g;
#pragma unroll
        for (int nt = 0; nt < 8; nt++) {
            const int c0 = bn + wn * 64 + nt * 8 + t4 * 2;
            const float b0 = bias[c0];
            const float b1 = bias[c0 + 1];
            float2 v0, v1;
            v0.x = acc[mt][nt][0] + b0; v0.y = acc[mt][nt][1] + b1;
            v1.x = acc[mt][nt][2] + b0; v1.y = acc[mt][nt][3] + b1;
            *(float2*)(C + (size_t)r0 * N + c0) = v0;
            *(float2*)(C + (size_t)(r0 + 8) * N + c0) = v1;
        }
    }
}

// ============================================================================
// Flash attention, tf32 mma.sync, fragment-major smem everywhere.
// BQ=128, BKV=64, 8 warps x 16 q-rows, 2 CTAs/SM.
//
// Layouts (float units):
//   QF: [warp*8+kb][lane] float4  {Q[g][t4], Q[g+8][t4], Q[g][t4+4], Q[g+8][t4+4]}
//   KF: [kb*8+nt][lane]  float2  {K[nt*8+g][kb*8+t4], K[nt*8+g][kb*8+t4+4]}
//   VF: [kb*8+nt][lane]  float2  {V[kb*8+t4][nt*8+g], V[kb*8+t4+4][nt*8+g]}
//   PF: per-warp, [kb][lane] float4 (same scheme as QF)
// ============================================================================
static constexpr int ABQ = 128, ABK = 64;
static constexpr int QF0 = 0;          // 8192 floats
static constexpr int KF0 = 8192;       // 4096 floats
static constexpr int VF0 = 12288;      // 4096 floats
static constexpr int PF0 = 16384;      // 8192 floats (8 warps x 1024)
static constexpr int ATTN_SMEM = 24576 * 4;   // 98304 B

__global__ __launch_bounds__(256, 2) void attn_mma(
    const float* __restrict__ qkv, float* __restrict__ out)
{
    extern __shared__ float sm[];
    const int tid = threadIdx.x;
    const int wid = tid >> 5;
    const int lane = tid & 31;
    const int g = lane >> 2;
    const int t4 = lane & 3;
    const int qi = gridDim.x - 1 - blockIdx.x;
    const int h = blockIdx.y;
    const int b = blockIdx.z;
    const int q0 = qi * ABQ;
    const size_t rs = (size_t)3 * En;
    const float* qbase = qkv + (size_t)b * Sn * rs + (size_t)h * Dn;
    const float* kbase = qbase + En;
    const float* vbase = qbase + 2 * En;

    // ---- Q tile -> fragment-major smem (once) ----
    for (int i = tid; i < ABQ * 16; i += 256) {
        const int row = i >> 4, c4 = (i & 15) * 4;
        float4 v = *(const float4*)(qbase + (size_t)(q0 + row) * rs + c4);
        float val[4];
        val[0] = tf32_rna(v.x * 0.125f);
        val[1] = tf32_rna(v.y * 0.125f);
        val[2] = tf32_rna(v.z * 0.125f);
        val[3] = tf32_rna(v.w * 0.125f);
        const int mb = row >> 4, rr = row & 15;
        const int gq = rr & 7, hi8 = rr >> 3;
#pragma unroll
        for (int e = 0; e < 4; e++) {
            const int c = c4 + e;
            const int kb = c >> 3, ci = c & 7;
            const int comp = hi8 + ((ci >> 2) << 1);
            sm[QF0 + ((mb * 8 + kb) * 32 + gq * 4 + (ci & 3)) * 4 + comp] = val[e];
        }
    }

    float m0 = -1e30f, m1 = -1e30f, l0 = 0.f, l1 = 0.f;
    float o[8][4];
#pragma unroll
    for (int nt = 0; nt < 8; nt++)
#pragma unroll
        for (int i = 0; i < 4; i++) o[nt][i] = 0.f;

    float* Pw = sm + PF0 + wid * 1024;
    const int ntiles = 2 * qi + 2;

    for (int jt = 0; jt < ntiles; jt++) {
        const int k0 = jt * ABK;
        __syncthreads();

        // ---- K tile -> paired-fragment smem (2 items/thread) ----
#pragma unroll
        for (int s = 0; s < 2; s++) {
            const int id = tid + s * 256;
            const int r = id >> 3, dc = id & 7;
            const float* kp = kbase + (size_t)(k0 + r) * rs + dc * 8;
            float4 v0 = *(const float4*)kp;
            float4 v1 = *(const float4*)(kp + 4);
            float4 w0, w1;
            w0.x = tf32_rna(v0.x); w0.y = tf32_rna(v1.x);
            w0.z = tf32_rna(v0.y); w0.w = tf32_rna(v1.y);
            w1.x = tf32_rna(v0.z); w1.y = tf32_rna(v1.z);
            w1.z = tf32_rna(v0.w); w1.w = tf32_rna(v1.w);
            const int base = KF0 + ((dc * 8 + (r >> 3)) * 32 + (r & 7) * 4) * 2;
            *(float4*)&sm[base] = w0;
            *(float4*)&sm[base + 4] = w1;
        }
        // ---- V tile -> paired-fragment smem (2 items/thread) ----
#pragma unroll
        for (int s = 0; s < 2; s++) {
            const int id = tid + s * 256;
            const int kb = id >> 6, t4v = (id >> 4) & 3, c4 = (id & 15) * 4;
            const float* vp = vbase + (size_t)(k0 + kb * 8 + t4v) * rs + c4;
            float4 a = *(const float4*)vp;
            float4 b2 = *(const float4*)(vp + 4 * rs);
            float av[4] = {tf32_rna(a.x), tf32_rna(a.y), tf32_rna(a.z), tf32_rna(a.w)};
            float bv[4] = {tf32_rna(b2.x), tf32_rna(b2.y), tf32_rna(b2.z), tf32_rna(b2.w)};
            const int nt = c4 >> 3;
            const int gbase = c4 & 7;
#pragma unroll
            for (int e = 0; e < 4; e++) {
                const int slot = (kb * 8 + nt) * 32 + (gbase + e) * 4 + t4v;
                float2 w; w.x = av[e]; w.y = bv[e];
                *(float2*)&sm[VF0 + slot * 2] = w;
            }
        }
        __syncthreads();

        // ---- S = (Q/8) @ K^T ----
        float acc[8][4];
#pragma unroll
        for (int nt = 0; nt < 8; nt++)
#pragma unroll
            for (int i = 0; i < 4; i++) acc[nt][i] = 0.f;

#pragma unroll
        for (int kb = 0; kb < 8; kb++) {
            uint4 aq = *(const uint4*)&sm[QF0 + ((wid * 8 + kb) * 32 + lane) * 4];
#pragma unroll
            for (int nt = 0; nt < 8; nt++) {
                uint2 bh = *(const uint2*)&sm[KF0 + ((kb * 8 + nt) * 32 + lane) * 2];
                mma_tf32(acc[nt], (const uint32_t*)&aq, (const uint32_t*)&bh);
            }
        }

        // ---- causal mask (diagonal-overlapping tiles only) ----
        if (jt >= ntiles - 2) {
            const int r0g = q0 + wid * 16 + g;
            const int r1g = r0g + 8;
#pragma unroll
            for (int nt = 0; nt < 8; nt++) {
                const int c = k0 + nt * 8 + t4 * 2;
                if (c > r0g)     acc[nt][0] = -1e30f;
                if (c + 1 > r0g) acc[nt][1] = -1e30f;
                if (c > r1g)     acc[nt][2] = -1e30f;
                if (c + 1 > r1g) acc[nt][3] = -1e30f;
            }
        }

        // ---- online softmax ----
        float mx0 = -1e30f, mx1 = -1e30f;
#pragma unroll
        for (int nt = 0; nt < 8; nt++) {
            mx0 = fmaxf(mx0, fmaxf(acc[nt][0], acc[nt][1]));
            mx1 = fmaxf(mx1, fmaxf(acc[nt][2], acc[nt][3]));
        }
        mx0 = fmaxf(mx0, __shfl_xor_sync(0xffffffffu, mx0, 1));
        mx0 = fmaxf(mx0, __shfl_xor_sync(0xffffffffu, mx0, 2));
        mx1 = fmaxf(mx1, __shfl_xor_sync(0xffffffffu, mx1, 1));
        mx1 = fmaxf(mx1, __shfl_xor_sync(0xffffffffu, mx1, 2));
        const float mn0 = fmaxf(m0, mx0);
        const float mn1 = fmaxf(m1, mx1);
        const float a0 = __expf(m0 - mn0);
        const float a1 = __expf(m1 - mn1);
        m0 = mn0; m1 = mn1;
        float s0 = 0.f, s1 = 0.f;
#pragma unroll
        for (int nt = 0; nt < 8; nt++) {
            acc[nt][0] = __expf(acc[nt][0] - m0); s0 += acc[nt][0];
            acc[nt][1] = __expf(acc[nt][1] - m0); s0 += acc[nt][1];
            acc[nt][2] = __expf(acc[nt][2] - m1); s1 += acc[nt][2];
            acc[nt][3] = __expf(acc[nt][3] - m1); s1 += acc[nt][3];
        }
        s0 += __shfl_xor_sync(0xffffffffu, s0, 1);
        s0 += __shfl_xor_sync(0xffffffffu, s0, 2);
        s1 += __shfl_xor_sync(0xffffffffu, s1, 1);
        s1 += __shfl_xor_sync(0xffffffffu, s1, 2);
        l0 = l0 * a0 + s0;
        l1 = l1 * a1 + s1;

        // ---- P -> warp-private fragment-major smem ----
        {
            const int ci = t4 * 2;
            const int comp = (t4 >= 2) ? 2 : 0;
            const int l4a = g * 4 + (ci & 3);
            const int l4b = g * 4 + ((ci + 1) & 3);
#pragma unroll
            for (int nt = 0; nt < 8; nt++) {
                float2 wa; wa.x = tf32_rna(acc[nt][0]); wa.y = tf32_rna(acc[nt][2]);
                float2 wb; wb.x = tf32_rna(acc[nt][1]); wb.y = tf32_rna(acc[nt][3]);
                *(float2*)&Pw[(nt * 32 + l4a) * 4 + comp] = wa;
                *(float2*)&Pw[(nt * 32 + l4b) * 4 + comp] = wb;
            }
        }
        __syncwarp();

        // ---- rescale O ----
#pragma unroll
        for (int nt = 0; nt < 8; nt++) {
            o[nt][0] *= a0; o[nt][1] *= a0;
            o[nt][2] *= a1; o[nt][3] *= a1;
        }

        // ---- O += P @ V ----
#pragma unroll
        for (int kb = 0; kb < 8; kb++) {
            uint4 ap = *(const uint4*)&Pw[(kb * 32 + lane) * 4];
#pragma unroll
            for (int nt = 0; nt < 8; nt++) {
                uint2 bh = *(const uint2*)&sm[VF0 + ((kb * 8 + nt) * 32 + lane) * 2];
                mma_tf32(o[nt], (const uint32_t*)&ap, (const uint32_t*)&bh);
            }
        }
        __syncwarp();
    }

    // ---- normalize + store ----
    const float i0 = 1.f / l0;
    const float i1 = 1.f / l1;
    const int r0g = q0 + wid * 16 + g;
#pragma unroll
    for (int nt = 0; nt < 8; nt++) {
        const int col = h * Dn + nt * 8 + t4 * 2;
        float2 v0, v1;
        v0.x = o[nt][0] * i0; v0.y = o[nt][1] * i0;
        v1.x = o[nt][2] * i1; v1.y = o[nt][3] * i1;
        *(float2*)(out + ((size_t)b * Sn + r0g) * En + col) = v0;
        *(float2*)(out + ((size_t)b * Sn + r0g + 8) * En + col) = v1;
    }
}

// ----------------------------------------------------------------------------
extern "C" void kernel_launch(void* const* d_in, const int* in_sizes, int n_in,
                              void* d_out, int out_size)
{
    const float* x     = (const float*)d_in[0];
    const float* w_in  = (const float*)d_in[1];
    const float* b_in  = (const float*)d_in[2];
    const float* w_out = (const float*)d_in[3];
    const float* b_out = (const float*)d_in[4];
    float* out = (float*)d_out;

    float* qkv = nullptr;
    float* attn = nullptr;
    cudaGetSymbolAddress((void**)&qkv, g_qkv);
    cudaGetSymbolAddress((void**)&attn, g_attn);

    const int M = Bn * Sn;  // 8192

    static bool attr_set = false;
    if (!attr_set) {
        cudaFuncSetAttribute(gemm_mma_bf16, cudaFuncAttributeMaxDynamicSharedMemorySize,
                             GEMM_SMEM);
        cudaFuncSetAttribute(attn_mma, cudaFuncAttributeMaxDynamicSharedMemorySize,
                             ATTN_SMEM);
        attr_set = true;
    }

    // 1) QKV projection (3xBF16 tensor cores)
    {
        dim3 grid((3 * En) / GBN, M / GBM);
        gemm_mma_bf16<<<grid, 256, GEMM_SMEM>>>(x, w_in, b_in, qkv, M, 3 * En, En);
    }

    // 2) Causal flash attention (tf32, fragment-major smem, 2 CTAs/SM)
    {
        dim3 grid(Sn / ABQ, Hn, Bn);
        attn_mma<<<grid, 256, ATTN_SMEM>>>(qkv, attn);
    }

    // 3) Output projection (3xBF16 tensor cores)
    {
        dim3 grid(En / GBN, M / GBM);
        gemm_mma_bf16<<<grid, 256, GEMM_SMEM>>>(attn, w_out, b_out, out, M, En, En);
    }
}

// round 9
// speedup vs baseline: 1.1290x; 1.1290x over previous
#include <cuda_runtime.h>
#include <cuda_bf16.h>
#include <cstdint>
#include <cstddef>

// Problem constants
static constexpr int Bn = 4;
static constexpr int Sn = 2048;
static constexpr int En = 1024;
static constexpr int Hn = 16;
static constexpr int Dn = 64;

// Scratch (device globals; no cudaMalloc allowed)
__device__ float g_qkv[(size_t)Bn * Sn * 3 * En];   // [B,S,3E]
__device__ float g_attn[(size_t)Bn * Sn * En];      // [B,S,E]

__device__ __forceinline__ float tf32_rna(float x) {
    uint32_t u;
    asm("cvt.rna.tf32.f32 %0, %1;" : "=r"(u) : "f"(x));
    return __uint_as_float(u);
}

// Warp-level tf32 MMA: D(16x8) += A(16x8) * B(8x8), fp32 acc.
__device__ __forceinline__ void mma_tf32(float* c, const uint32_t* a, const uint32_t* b) {
    asm volatile(
        "mma.sync.aligned.m16n8k8.row.col.f32.tf32.tf32.f32 "
        "{%0,%1,%2,%3}, {%4,%5,%6,%7}, {%8,%9}, {%0,%1,%2,%3};"
        : "+f"(c[0]), "+f"(c[1]), "+f"(c[2]), "+f"(c[3])
        : "r"(a[0]), "r"(a[1]), "r"(a[2]), "r"(a[3]), "r"(b[0]), "r"(b[1]));
}

// Warp-level bf16 MMA: D(16x8) += A(16x16) * B(16x8), fp32 acc.
__device__ __forceinline__ void mma_bf16(float* c, const uint32_t* a, const uint32_t* b) {
    asm volatile(
        "mma.sync.aligned.m16n8k16.row.col.f32.bf16.bf16.f32 "
        "{%0,%1,%2,%3}, {%4,%5,%6,%7}, {%8,%9}, {%0,%1,%2,%3};"
        : "+f"(c[0]), "+f"(c[1]), "+f"(c[2]), "+f"(c[3])
        : "r"(a[0]), "r"(a[1]), "r"(a[2]), "r"(a[3]), "r"(b[0]), "r"(b[1]));
}

__device__ __forceinline__ void split_pack_bf16(float x0, float x1,
                                                uint32_t& hi, uint32_t& lo) {
    __nv_bfloat162 h = __floats2bfloat162_rn(x0, x1);
    float f0 = __bfloat162float(h.x);
    float f1 = __bfloat162float(h.y);
    __nv_bfloat162 l = __floats2bfloat162_rn(x0 - f0, x1 - f1);
    hi = *(uint32_t*)&h;
    lo = *(uint32_t*)&l;
}

__device__ __forceinline__ void cp16(uint32_t dst, const void* src) {
    asm volatile("cp.async.ca.shared.global [%0], [%1], 16;"
                 :: "r"(dst), "l"(src) : "memory");
}

// ============================================================================
// 3xBF16 tensor-core GEMM (R7 proven): C = A @ Bw^T + bias
// ============================================================================
static constexpr int GBM = 128, GBN = 128, GBK = 32;
static constexpr int STAGE_E = 16384;
static constexpr int GEMM_SMEM = 2 * STAGE_E * 2;    // 65536 bytes

__global__ __launch_bounds__(256, 2) void gemm_mma_bf16(
    const float* __restrict__ A, const float* __restrict__ Bw,
    const float* __restrict__ bias, float* __restrict__ C,
    int M, int N, int K)
{
    extern __shared__ uint16_t smu[];
    uint32_t* sm32 = (uint32_t*)smu;

    const int tid = threadIdx.x;
    const int wid = tid >> 5;
    const int lane = tid & 31;
    const int g = lane >> 2;
    const int t4 = lane & 3;
    const int wm = wid >> 1;
    const int wn = wid & 1;
    const int bm = blockIdx.y * GBM;
    const int bn = blockIdx.x * GBN;
    const int kT = K / GBK;

    float acc[2][8][4];
#pragma unroll
    for (int mt = 0; mt < 2; mt++)
#pragma unroll
        for (int nt = 0; nt < 8; nt++)
#pragma unroll
            for (int i = 0; i < 4; i++) acc[mt][nt][i] = 0.f;

    const int lrow = tid >> 3;
    const int lq = tid & 7;
    const int k0l = lq * 4;
    const int kblkL = k0l >> 4;
    const int kcL = k0l & 15;
    const int khalfL = kcL >> 3;
    const int t4L = (kcL & 7) >> 1;

    int aw[4], bw2[4];
#pragma unroll
    for (int s = 0; s < 4; s++) {
        const int row = lrow + s * 32;
        const int mblk = row >> 4, r16 = row & 15;
        const int halfA = r16 >> 3, gA = r16 & 7;
        const int aoff = (mblk * 2 + kblkL) * 256 + gA * 32 + khalfL * 4 + halfA * 2;
        aw[s] = (aoff >> 1) + t4L * 4;
        const int nblk = row >> 3, gB = row & 7;
        const int boff = (nblk * 2 + kblkL) * 128 + gB * 16 + khalfL * 2;
        bw2[s] = (boff >> 1) + t4L * 2;
    }

    float4 pa[4], pb[4];
#pragma unroll
    for (int s = 0; s < 4; s++) {
        const int row = lrow + s * 32;
        pa[s] = *(const float4*)(A + (size_t)(bm + row) * K + k0l);
        pb[s] = *(const float4*)(Bw + (size_t)(bn + row) * K + k0l);
    }

    {
        uint32_t* AH = sm32;
        uint32_t* AL = sm32 + 2048;
        uint32_t* BH = sm32 + 4096;
        uint32_t* BL = sm32 + 6144;
#pragma unroll
        for (int s = 0; s < 4; s++) {
            uint32_t h01, l01, h23, l23;
            split_pack_bf16(pa[s].x, pa[s].y, h01, l01);
            split_pack_bf16(pa[s].z, pa[s].w, h23, l23);
            AH[aw[s]] = h01; AH[aw[s] + 4] = h23;
            AL[aw[s]] = l01; AL[aw[s] + 4] = l23;
            split_pack_bf16(pb[s].x, pb[s].y, h01, l01);
            split_pack_bf16(pb[s].z, pb[s].w, h23, l23);
            BH[bw2[s]] = h01; BH[bw2[s] + 2] = h23;
            BL[bw2[s]] = l01; BL[bw2[s] + 2] = l23;
        }
    }
    __syncthreads();

    for (int j = 0; j < kT; j++) {
        const int st = j & 1;
        if (j + 1 < kT) {
            const int k0 = (j + 1) * GBK + k0l;
#pragma unroll
            for (int s = 0; s < 4; s++) {
                const int row = lrow + s * 32;
                pa[s] = *(const float4*)(A + (size_t)(bm + row) * K + k0);
                pb[s] = *(const float4*)(Bw + (size_t)(bn + row) * K + k0);
            }
        }

        const uint16_t* stg = smu + st * STAGE_E;
#pragma unroll
        for (int kblk = 0; kblk < 2; kblk++) {
            uint4 ahi[2], alo[2];
#pragma unroll
            for (int mt = 0; mt < 2; mt++) {
                const int mblk = wm * 2 + mt;
                const int base = (mblk * 2 + kblk) * 256 + g * 32 + t4 * 8;
                ahi[mt] = *(const uint4*)(stg + base);
                alo[mt] = *(const uint4*)(stg + 4096 + base);
            }
#pragma unroll
            for (int nt = 0; nt < 8; nt++) {
                const int nblk = wn * 8 + nt;
                const int bbase = (nblk * 2 + kblk) * 128 + g * 16 + t4 * 4;
                uint2 bh = *(const uint2*)(stg + 8192 + bbase);
                uint2 bl = *(const uint2*)(stg + 12288 + bbase);
#pragma unroll
                for (int mt = 0; mt < 2; mt++) {
                    mma_bf16(acc[mt][nt], (const uint32_t*)&ahi[mt], (const uint32_t*)&bh);
                    mma_bf16(acc[mt][nt], (const uint32_t*)&ahi[mt], (const uint32_t*)&bl);
                    mma_bf16(acc[mt][nt], (const uint32_t*)&alo[mt], (const uint32_t*)&bh);
                }
            }
        }

        if (j + 1 < kT) {
            const int so = st ^ 1;
            uint32_t* AH = sm32 + so * (STAGE_E / 2);
            uint32_t* AL = AH + 2048;
            uint32_t* BH = AH + 4096;
            uint32_t* BL = AH + 6144;
#pragma unroll
            for (int s = 0; s < 4; s++) {
                uint32_t h01, l01, h23, l23;
                split_pack_bf16(pa[s].x, pa[s].y, h01, l01);
                split_pack_bf16(pa[s].z, pa[s].w, h23, l23);
                AH[aw[s]] = h01; AH[aw[s] + 4] = h23;
                AL[aw[s]] = l01; AL[aw[s] + 4] = l23;
                split_pack_bf16(pb[s].x, pb[s].y, h01, l01);
                split_pack_bf16(pb[s].z, pb[s].w, h23, l23);
                BH[bw2[s]] = h01; BH[bw2[s] + 2] = h23;
                BL[bw2[s]] = l01; BL[bw2[s] + 2] = l23;
            }
        }
        __syncthreads();
    }

#pragma unroll
    for (int mt = 0; mt < 2; mt++) {
        const int r0 = bm + wm * 32 + mt * 16 + g;
#pragma unroll
        for (int nt = 0; nt < 8; nt++) {
            const int c0 = bn + wn * 64 + nt * 8 + t4 * 2;
            const float b0 = bias[c0];
            const float b1 = bias[c0 + 1];
            float2 v0, v1;
            v0.x = acc[mt][nt][0] + b0; v0.y = acc[mt][nt][1] + b1;
            v1.x = acc[mt][nt][2] + b0; v1.y = acc[mt][nt][3] + b1;
            *(float2*)(C + (size_t)r0 * N + c0) = v0;
            *(float2*)(C + (size_t)(r0 + 8) * N + c0) = v1;
        }
    }
}

// ============================================================================
// Flash attention, tf32 mma.sync, cp.async double-buffered K/V.
// BQ=128, BKV=32, 8 warps x 16 q-rows, 2 CTAs/SM.
// K/V enter smem as raw fp32 via cp.async; MMA truncates to tf32 in HW.
// ============================================================================
static constexpr int ABQ = 128, ABK = 32, APAD = 68, PPAD = 36;
static constexpr int QF0 = 0;              // 128*68 = 8704 floats
static constexpr int KF0 = 8704;           // 2 bufs * (32*68=2176)
static constexpr int VF0 = 13056;          // 2 bufs * 2176
static constexpr int PF0 = 17408;          // 8 warps * 16*36 = 4608
static constexpr int ATTN_SMEM = 22016 * 4;   // 88064 B

__global__ __launch_bounds__(256, 2) void attn_mma(
    const float* __restrict__ qkv, float* __restrict__ out)
{
    extern __shared__ float sm[];
    const int tid = threadIdx.x;
    const int wid = tid >> 5;
    const int lane = tid & 31;
    const int g = lane >> 2;
    const int t4 = lane & 3;
    const int qi = gridDim.x - 1 - blockIdx.x;   // largest workload first
    const int h = blockIdx.y;
    const int b = blockIdx.z;
    const int q0 = qi * ABQ;
    const size_t rs = (size_t)3 * En;
    const float* qbase = qkv + (size_t)b * Sn * rs + (size_t)h * Dn;
    const float* kbase = qbase + En;
    const float* vbase = qbase + 2 * En;
    const uint32_t smem_base = (uint32_t)__cvta_generic_to_shared(sm);

    // issue cp.async for K/V tile jt into buffer bi (1024 16B chunks total)
    auto issue_kv = [&](int jt, int bi) {
        const int k0 = jt * ABK;
#pragma unroll
        for (int s = 0; s < 4; s++) {
            const int c = tid + s * 256;
            const int isV = c >> 9;
            const int cc = c & 511;
            const int row = cc >> 4, q = cc & 15;
            const float* src = (isV ? vbase : kbase) + (size_t)(k0 + row) * rs + q * 4;
            const int dstf = (isV ? VF0 : KF0) + bi * 2176 + row * APAD + q * 4;
            cp16(smem_base + dstf * 4, src);
        }
        asm volatile("cp.async.commit_group;" ::: "memory");
    };

    issue_kv(0, 0);

    // ---- Q tile -> smem (scaled, rna-truncated), row-major pad 68 ----
    for (int i = tid; i < ABQ * 16; i += 256) {
        const int row = i >> 4, c4 = (i & 15) * 4;
        float4 v = *(const float4*)(qbase + (size_t)(q0 + row) * rs + c4);
        float4 hi;
        hi.x = tf32_rna(v.x * 0.125f);
        hi.y = tf32_rna(v.y * 0.125f);
        hi.z = tf32_rna(v.z * 0.125f);
        hi.w = tf32_rna(v.w * 0.125f);
        *(float4*)&sm[QF0 + row * APAD + c4] = hi;
    }

    float m0 = -1e30f, m1 = -1e30f, l0 = 0.f, l1 = 0.f;
    float o[8][4];
#pragma unroll
    for (int nt = 0; nt < 8; nt++)
#pragma unroll
        for (int i = 0; i < 4; i++) o[nt][i] = 0.f;

    const int wrow = wid * 16;
    float* Pw = sm + PF0 + wid * (16 * PPAD);
    const int ntiles = 4 * qi + 4;

    for (int jt = 0; jt < ntiles; jt++) {
        const int bi = jt & 1;
        const int k0 = jt * ABK;
        if (jt + 1 < ntiles) {
            issue_kv(jt + 1, bi ^ 1);
            asm volatile("cp.async.wait_group 1;" ::: "memory");
        } else {
            asm volatile("cp.async.wait_group 0;" ::: "memory");
        }
        __syncthreads();

        const float* Kb = sm + KF0 + bi * 2176;
        const float* Vb = sm + VF0 + bi * 2176;

        // ---- S = (Q/8) @ K^T ----
        float acc[4][4];
#pragma unroll
        for (int nt = 0; nt < 4; nt++)
#pragma unroll
            for (int i = 0; i < 4; i++) acc[nt][i] = 0.f;

#pragma unroll
        for (int kb = 0; kb < 8; kb++) {
            uint32_t aq[4];
            aq[0] = __float_as_uint(sm[QF0 + (wrow + g) * APAD + kb * 8 + t4]);
            aq[1] = __float_as_uint(sm[QF0 + (wrow + g + 8) * APAD + kb * 8 + t4]);
            aq[2] = __float_as_uint(sm[QF0 + (wrow + g) * APAD + kb * 8 + t4 + 4]);
            aq[3] = __float_as_uint(sm[QF0 + (wrow + g + 8) * APAD + kb * 8 + t4 + 4]);
#pragma unroll
            for (int nt = 0; nt < 4; nt++) {
                uint32_t bh[2];
                bh[0] = __float_as_uint(Kb[(nt * 8 + g) * APAD + kb * 8 + t4]);
                bh[1] = __float_as_uint(Kb[(nt * 8 + g) * APAD + kb * 8 + t4 + 4]);
                mma_tf32(acc[nt], aq, bh);
            }
        }

        // ---- causal mask (4 diagonal-overlapping tiles) ----
        if (jt >= ntiles - 4) {
            const int r0g = q0 + wrow + g;
            const int r1g = r0g + 8;
#pragma unroll
            for (int nt = 0; nt < 4; nt++) {
                const int c = k0 + nt * 8 + t4 * 2;
                if (c > r0g)     acc[nt][0] = -1e30f;
                if (c + 1 > r0g) acc[nt][1] = -1e30f;
                if (c > r1g)     acc[nt][2] = -1e30f;
                if (c + 1 > r1g) acc[nt][3] = -1e30f;
            }
        }

        // ---- online softmax ----
        float mx0 = -1e30f, mx1 = -1e30f;
#pragma unroll
        for (int nt = 0; nt < 4; nt++) {
            mx0 = fmaxf(mx0, fmaxf(acc[nt][0], acc[nt][1]));
            mx1 = fmaxf(mx1, fmaxf(acc[nt][2], acc[nt][3]));
        }
        mx0 = fmaxf(mx0, __shfl_xor_sync(0xffffffffu, mx0, 1));
        mx0 = fmaxf(mx0, __shfl_xor_sync(0xffffffffu, mx0, 2));
        mx1 = fmaxf(mx1, __shfl_xor_sync(0xffffffffu, mx1, 1));
        mx1 = fmaxf(mx1, __shfl_xor_sync(0xffffffffu, mx1, 2));
        const float mn0 = fmaxf(m0, mx0);
        const float mn1 = fmaxf(m1, mx1);
        const float a0 = __expf(m0 - mn0);
        const float a1 = __expf(m1 - mn1);
        m0 = mn0; m1 = mn1;
        float s0 = 0.f, s1 = 0.f;
#pragma unroll
        for (int nt = 0; nt < 4; nt++) {
            acc[nt][0] = __expf(acc[nt][0] - m0); s0 += acc[nt][0];
            acc[nt][1] = __expf(acc[nt][1] - m0); s0 += acc[nt][1];
            acc[nt][2] = __expf(acc[nt][2] - m1); s1 += acc[nt][2];
            acc[nt][3] = __expf(acc[nt][3] - m1); s1 += acc[nt][3];
        }
        s0 += __shfl_xor_sync(0xffffffffu, s0, 1);
        s0 += __shfl_xor_sync(0xffffffffu, s0, 2);
        s1 += __shfl_xor_sync(0xffffffffu, s1, 1);
        s1 += __shfl_xor_sync(0xffffffffu, s1, 2);
        l0 = l0 * a0 + s0;
        l1 = l1 * a1 + s1;

        // ---- P -> warp-private smem ----
#pragma unroll
        for (int nt = 0; nt < 4; nt++) {
            Pw[g * PPAD + nt * 8 + t4 * 2]           = tf32_rna(acc[nt][0]);
            Pw[g * PPAD + nt * 8 + t4 * 2 + 1]       = tf32_rna(acc[nt][1]);
            Pw[(g + 8) * PPAD + nt * 8 + t4 * 2]     = tf32_rna(acc[nt][2]);
            Pw[(g + 8) * PPAD + nt * 8 + t4 * 2 + 1] = tf32_rna(acc[nt][3]);
        }
        __syncwarp();

        // ---- rescale O ----
#pragma unroll
        for (int nt = 0; nt < 8; nt++) {
            o[nt][0] *= a0; o[nt][1] *= a0;
            o[nt][2] *= a1; o[nt][3] *= a1;
        }

        // ---- O += P @ V ----
#pragma unroll
        for (int kb = 0; kb < 4; kb++) {
            uint32_t ap[4];
            ap[0] = __float_as_uint(Pw[g * PPAD + kb * 8 + t4]);
            ap[1] = __float_as_uint(Pw[(g + 8) * PPAD + kb * 8 + t4]);
            ap[2] = __float_as_uint(Pw[g * PPAD + kb * 8 + t4 + 4]);
            ap[3] = __float_as_uint(Pw[(g + 8) * PPAD + kb * 8 + t4 + 4]);
#pragma unroll
            for (int nt = 0; nt < 8; nt++) {
                uint32_t bh[2];
                bh[0] = __float_as_uint(Vb[(kb * 8 + t4) * APAD + nt * 8 + g]);
                bh[1] = __float_as_uint(Vb[(kb * 8 + t4 + 4) * APAD + nt * 8 + g]);
                mma_tf32(o[nt], ap, bh);
            }
        }
        __syncwarp();
        __syncthreads();   // all warps done with buf bi before it is refilled
    }

    // ---- normalize + store ----
    const float i0 = 1.f / l0;
    const float i1 = 1.f / l1;
    const int r0g = q0 + wrow + g;
#pragma unroll
    for (int nt = 0; nt < 8; nt++) {
        const int col = h * Dn + nt * 8 + t4 * 2;
        float2 v0, v1;
        v0.x = o[nt][0] * i0; v0.y = o[nt][1] * i0;
        v1.x = o[nt][2] * i1; v1.y = o[nt][3] * i1;
        *(float2*)(out + ((size_t)b * Sn + r0g) * En + col) = v0;
        *(float2*)(out + ((size_t)b * Sn + r0g + 8) * En + col) = v1;
    }
}

// ----------------------------------------------------------------------------
extern "C" void kernel_launch(void* const* d_in, const int* in_sizes, int n_in,
                              void* d_out, int out_size)
{
    const float* x     = (const float*)d_in[0];
    const float* w_in  = (const float*)d_in[1];
    const float* b_in  = (const float*)d_in[2];
    const float* w_out = (const float*)d_in[3];
    const float* b_out = (const float*)d_in[4];
    float* out = (float*)d_out;

    float* qkv = nullptr;
    float* attn = nullptr;
    cudaGetSymbolAddress((void**)&qkv, g_qkv);
    cudaGetSymbolAddress((void**)&attn, g_attn);

    const int M = Bn * Sn;  // 8192

    static bool attr_set = false;
    if (!attr_set) {
        cudaFuncSetAttribute(gemm_mma_bf16, cudaFuncAttributeMaxDynamicSharedMemorySize,
                             GEMM_SMEM);
        cudaFuncSetAttribute(attn_mma, cudaFuncAttributeMaxDynamicSharedMemorySize,
                             ATTN_SMEM);
        attr_set = true;
    }

    // 1) QKV projection (3xBF16 tensor cores)
    {
        dim3 grid((3 * En) / GBN, M / GBM);
        gemm_mma_bf16<<<grid, 256, GEMM_SMEM>>>(x, w_in, b_in, qkv, M, 3 * En, En);
    }

    // 2) Causal flash attention (tf32, cp.async double-buffered K/V)
    {
        dim3 grid(Sn / ABQ, Hn, Bn);
        attn_mma<<<grid, 256, ATTN_SMEM>>>(qkv, attn);
    }

    // 3) Output projection (3xBF16 tensor cores)
    {
        dim3 grid(En / GBN, M / GBM);
        gemm_mma_bf16<<<grid, 256, GEMM_SMEM>>>(attn, w_out, b_out, out, M, En, En);
    }
}

// round 10
// speedup vs baseline: 1.2152x; 1.0764x over previous
#include <cuda_runtime.h>
#include <cuda_bf16.h>
#include <cstdint>
#include <cstddef>

// Problem constants
static constexpr int Bn = 4;
static constexpr int Sn = 2048;
static constexpr int En = 1024;
static constexpr int Hn = 16;
static constexpr int Dn = 64;

// Scratch (device globals; no cudaMalloc allowed)
__device__ float g_qkv[(size_t)Bn * Sn * 3 * En];   // [B,S,3E]
__device__ float g_attn[(size_t)Bn * Sn * En];      // [B,S,E]

// Pre-split bf16 hi/lo operand tiles (fragment-major layout)
__device__ uint4 g_xh[1048576], g_xl[1048576];      // x:    [64][32][4096 bf16]
__device__ uint4 g_ah[1048576], g_al[1048576];      // attn: [64][32][4096 bf16]
__device__ uint4 g_wih[393216], g_wil[393216];      // w_in: [24][32][4096 bf16]
__device__ uint4 g_woh[131072], g_wol[131072];      // w_out:[ 8][32][4096 bf16]

__device__ __forceinline__ float tf32_rna(float x) {
    uint32_t u;
    asm("cvt.rna.tf32.f32 %0, %1;" : "=r"(u) : "f"(x));
    return __uint_as_float(u);
}

__device__ __forceinline__ void mma_tf32(float* c, const uint32_t* a, const uint32_t* b) {
    asm volatile(
        "mma.sync.aligned.m16n8k8.row.col.f32.tf32.tf32.f32 "
        "{%0,%1,%2,%3}, {%4,%5,%6,%7}, {%8,%9}, {%0,%1,%2,%3};"
        : "+f"(c[0]), "+f"(c[1]), "+f"(c[2]), "+f"(c[3])
        : "r"(a[0]), "r"(a[1]), "r"(a[2]), "r"(a[3]), "r"(b[0]), "r"(b[1]));
}

__device__ __forceinline__ void mma_bf16(float* c, const uint32_t* a, const uint32_t* b) {
    asm volatile(
        "mma.sync.aligned.m16n8k16.row.col.f32.bf16.bf16.f32 "
        "{%0,%1,%2,%3}, {%4,%5,%6,%7}, {%8,%9}, {%0,%1,%2,%3};"
        : "+f"(c[0]), "+f"(c[1]), "+f"(c[2]), "+f"(c[3])
        : "r"(a[0]), "r"(a[1]), "r"(a[2]), "r"(a[3]), "r"(b[0]), "r"(b[1]));
}

__device__ __forceinline__ void split_pack_bf16(float x0, float x1,
                                                uint32_t& hi, uint32_t& lo) {
    __nv_bfloat162 h = __floats2bfloat162_rn(x0, x1);
    float f0 = __bfloat162float(h.x);
    float f1 = __bfloat162float(h.y);
    __nv_bfloat162 l = __floats2bfloat162_rn(x0 - f0, x1 - f1);
    hi = *(uint32_t*)&h;
    lo = *(uint32_t*)&l;
}

__device__ __forceinline__ void cp16(uint32_t dst, const void* src) {
    asm volatile("cp.async.ca.shared.global [%0], [%1], 16;"
                 :: "r"(dst), "l"(src) : "memory");
}

// ============================================================================
// Prep kernels: split fp32 -> bf16 hi/lo in fragment-major tile layout.
// A tile [128m x 32k]: blk=(m16*2+kblk) 256-bf16 blocks; u32idx within blk =
//   g*16 + t4*4 + khalf*2 + half ; element = A[m16*16+half*8+g][kblk*16+khalf*8+t4*2+{0,1}]
// B tile [128n x 32k]: blk=(nblk*2+kblk) 128-bf16 blocks;
//   f = t4*4+khalf*2+klo -> element B[nblk*8+g][kblk*16+khalf*8+t4*2+klo]
// ============================================================================
__global__ __launch_bounds__(256) void prep_a(
    const float* __restrict__ A, uint4* __restrict__ H, uint4* __restrict__ L, int K)
{
    const size_t o = (size_t)blockIdx.x * 256 + threadIdx.x;
    const int u4 = (int)(o & 511);
    const int tile = (int)(o >> 9);
    const int kT = K >> 5;
    const int mt = tile / kT, kt = tile % kT;
    const int blkPair = u4 >> 5;            // m16*2+kblk
    const int m16 = blkPair >> 1, kblk = blkPair & 1;
    const int rem = u4 & 31;
    const int g = rem >> 2, t4 = rem & 3;
    const int r0 = mt * 128 + m16 * 16 + g;
    const int kb = kt * 32 + kblk * 16 + t4 * 2;
    const float* p0 = A + (size_t)r0 * K + kb;
    const float* p1 = p0 + (size_t)8 * K;
    const float2 a00 = *(const float2*)p0;
    const float2 a10 = *(const float2*)p1;
    const float2 a01 = *(const float2*)(p0 + 8);
    const float2 a11 = *(const float2*)(p1 + 8);
    uint4 hv, lv;
    split_pack_bf16(a00.x, a00.y, hv.x, lv.x);
    split_pack_bf16(a10.x, a10.y, hv.y, lv.y);
    split_pack_bf16(a01.x, a01.y, hv.z, lv.z);
    split_pack_bf16(a11.x, a11.y, hv.w, lv.w);
    H[o] = hv; L[o] = lv;
}

__global__ __launch_bounds__(256) void prep_b(
    const float* __restrict__ B, uint4* __restrict__ H, uint4* __restrict__ L, int K)
{
    const size_t o = (size_t)blockIdx.x * 256 + threadIdx.x;
    const int u4 = (int)(o & 511);
    const int tile = (int)(o >> 9);
    const int kT = K >> 5;
    const int nt = tile / kT, kt = tile % kT;
    const int blkPair = u4 >> 4;            // nblk*2+kblk
    const int nblk = blkPair >> 1, kblk = blkPair & 1;
    const int rem = u4 & 15;
    const int g = rem >> 1, j = rem & 1;
    const int n = nt * 128 + nblk * 8 + g;
    const int kb = kt * 32 + kblk * 16 + j * 4;
    const float4 p = *(const float4*)(B + (size_t)n * K + kb);
    const float4 q = *(const float4*)(B + (size_t)n * K + kb + 8);
    uint4 hv, lv;
    split_pack_bf16(p.x, p.y, hv.x, lv.x);
    split_pack_bf16(q.x, q.y, hv.y, lv.y);
    split_pack_bf16(p.z, p.w, hv.z, lv.z);
    split_pack_bf16(q.z, q.w, hv.w, lv.w);
    H[o] = hv; L[o] = lv;
}

// ============================================================================
// 3xBF16 tensor-core GEMM on pre-split fragment-major operands.
// C[M,N] = A @ B^T + bias ; 128x128 tile, BK=32, 3-stage cp.async pipeline.
// roundFromTile: CTAs with blockIdx.x >= roundFromTile round output to tf32
// (used to pre-round K/V so attention's cp.async RZ-truncation is exact).
// ============================================================================
static constexpr int STAGE_E = 16384;                 // bf16 per stage (32 KB)
static constexpr int GEMM_SMEM = 3 * STAGE_E * 2;     // 98304 bytes

__global__ __launch_bounds__(256, 2) void gemm_pre(
    const uint4* __restrict__ AH, const uint4* __restrict__ AL,
    const uint4* __restrict__ BH, const uint4* __restrict__ BL,
    const float* __restrict__ bias, float* __restrict__ C,
    int N, int kT, int roundFromTile)
{
    extern __shared__ uint16_t smu[];
    const int tid = threadIdx.x;
    const int wid = tid >> 5;
    const int lane = tid & 31;
    const int g = lane >> 2;
    const int t4 = lane & 3;
    const int wm = wid >> 1;
    const int wn = wid & 1;
    const int mt = blockIdx.y;
    const int nt = blockIdx.x;
    const uint32_t smem_base = (uint32_t)__cvta_generic_to_shared(smu);

    const size_t atile = (size_t)mt * kT;
    const size_t btile = (size_t)nt * kT;

    // Issue one stage's cp.async (2048 x 16B chunks / 256 threads = 8 each).
    auto issue = [&](int j, int st) {
        const uint32_t dst0 = smem_base + st * 32768;
#pragma unroll
        for (int s = 0; s < 8; s++) {
            const int arr = s >> 1;                // 0:AH 1:AL 2:BH 3:BL
            const int off = tid + (s & 1) * 256;   // 0..511 (uint4 units)
            const uint4* bp = (arr == 0) ? AH : (arr == 1) ? AL
                             : (arr == 2) ? BH : BL;
            const size_t tb = (arr < 2) ? atile : btile;
            cp16(dst0 + arr * 8192 + off * 16, bp + (tb + j) * 512 + off);
        }
        asm volatile("cp.async.commit_group;" ::: "memory");
    };

    float acc[2][8][4];
#pragma unroll
    for (int mtl = 0; mtl < 2; mtl++)
#pragma unroll
        for (int ntl = 0; ntl < 8; ntl++)
#pragma unroll
            for (int i = 0; i < 4; i++) acc[mtl][ntl][i] = 0.f;

    issue(0, 0);
    issue(1, 1);

    for (int j = 0; j < kT; j++) {
        if (j + 2 < kT) {
            asm volatile("cp.async.wait_group 1;" ::: "memory");
        } else {
            asm volatile("cp.async.wait_group 0;" ::: "memory");
        }
        __syncthreads();
        if (j + 2 < kT) issue(j + 2, (j + 2) % 3);

        const uint16_t* stg = smu + (j % 3) * STAGE_E;
#pragma unroll
        for (int kblk = 0; kblk < 2; kblk++) {
            uint4 ahi[2], alo[2];
#pragma unroll
            for (int mtl = 0; mtl < 2; mtl++) {
                const int mblk = wm * 2 + mtl;
                const int base = (mblk * 2 + kblk) * 256 + g * 32 + t4 * 8;
                ahi[mtl] = *(const uint4*)(stg + base);
                alo[mtl] = *(const uint4*)(stg + 4096 + base);
            }
#pragma unroll
            for (int ntl = 0; ntl < 8; ntl++) {
                const int nblk = wn * 8 + ntl;
                const int bbase = (nblk * 2 + kblk) * 128 + g * 16 + t4 * 4;
                uint2 bh = *(const uint2*)(stg + 8192 + bbase);
                uint2 bl = *(const uint2*)(stg + 12288 + bbase);
#pragma unroll
                for (int mtl = 0; mtl < 2; mtl++) {
                    mma_bf16(acc[mtl][ntl], (const uint32_t*)&ahi[mtl], (const uint32_t*)&bh);
                    mma_bf16(acc[mtl][ntl], (const uint32_t*)&ahi[mtl], (const uint32_t*)&bl);
                    mma_bf16(acc[mtl][ntl], (const uint32_t*)&alo[mtl], (const uint32_t*)&bh);
                }
            }
        }
        __syncthreads();
    }

    // Epilogue: bias, optional tf32-RNA pre-round (uniform per CTA), store.
    const bool roundT = (nt >= roundFromTile);
    const int bm = mt * 128;
    const int bn = nt * 128;
#pragma unroll
    for (int mtl = 0; mtl < 2; mtl++) {
        const int r0 = bm + wm * 32 + mtl * 16 + g;
#pragma unroll
        for (int ntl = 0; ntl < 8; ntl++) {
            const int c0 = bn + wn * 64 + ntl * 8 + t4 * 2;
            const float b0 = bias[c0];
            const float b1 = bias[c0 + 1];
            float2 v0, v1;
            v0.x = acc[mtl][ntl][0] + b0; v0.y = acc[mtl][ntl][1] + b1;
            v1.x = acc[mtl][ntl][2] + b0; v1.y = acc[mtl][ntl][3] + b1;
            if (roundT) {
                v0.x = tf32_rna(v0.x); v0.y = tf32_rna(v0.y);
                v1.x = tf32_rna(v1.x); v1.y = tf32_rna(v1.y);
            }
            *(float2*)(C + (size_t)r0 * N + c0) = v0;
            *(float2*)(C + (size_t)(r0 + 8) * N + c0) = v1;
        }
    }
}

// ============================================================================
// Flash attention (R9 proven): tf32 mma.sync, cp.async double-buffered K/V.
// BQ=128, BKV=32, 8 warps x 16 q-rows, 2 CTAs/SM.
// K/V in g_qkv are pre-rounded to tf32 -> HW RZ truncation is exact.
// ============================================================================
static constexpr int ABQ = 128, ABK = 32, APAD = 68, PPAD = 36;
static constexpr int QF0 = 0;              // 128*68 = 8704 floats
static constexpr int KF0 = 8704;           // 2 bufs * (32*68=2176)
static constexpr int VF0 = 13056;          // 2 bufs * 2176
static constexpr int PF0 = 17408;          // 8 warps * 16*36 = 4608
static constexpr int ATTN_SMEM = 22016 * 4;   // 88064 B

__global__ __launch_bounds__(256, 2) void attn_mma(
    const float* __restrict__ qkv, float* __restrict__ out)
{
    extern __shared__ float sm[];
    const int tid = threadIdx.x;
    const int wid = tid >> 5;
    const int lane = tid & 31;
    const int g = lane >> 2;
    const int t4 = lane & 3;
    const int qi = gridDim.x - 1 - blockIdx.x;
    const int h = blockIdx.y;
    const int b = blockIdx.z;
    const int q0 = qi * ABQ;
    const size_t rs = (size_t)3 * En;
    const float* qbase = qkv + (size_t)b * Sn * rs + (size_t)h * Dn;
    const float* kbase = qbase + En;
    const float* vbase = qbase + 2 * En;
    const uint32_t smem_base = (uint32_t)__cvta_generic_to_shared(sm);

    auto issue_kv = [&](int jt, int bi) {
        const int k0 = jt * ABK;
#pragma unroll
        for (int s = 0; s < 4; s++) {
            const int c = tid + s * 256;
            const int isV = c >> 9;
            const int cc = c & 511;
            const int row = cc >> 4, q = cc & 15;
            const float* src = (isV ? vbase : kbase) + (size_t)(k0 + row) * rs + q * 4;
            const int dstf = (isV ? VF0 : KF0) + bi * 2176 + row * APAD + q * 4;
            cp16(smem_base + dstf * 4, src);
        }
        asm volatile("cp.async.commit_group;" ::: "memory");
    };

    issue_kv(0, 0);

    for (int i = tid; i < ABQ * 16; i += 256) {
        const int row = i >> 4, c4 = (i & 15) * 4;
        float4 v = *(const float4*)(qbase + (size_t)(q0 + row) * rs + c4);
        float4 hi;
        hi.x = tf32_rna(v.x * 0.125f);
        hi.y = tf32_rna(v.y * 0.125f);
        hi.z = tf32_rna(v.z * 0.125f);
        hi.w = tf32_rna(v.w * 0.125f);
        *(float4*)&sm[QF0 + row * APAD + c4] = hi;
    }

    float m0 = -1e30f, m1 = -1e30f, l0 = 0.f, l1 = 0.f;
    float o[8][4];
#pragma unroll
    for (int nt = 0; nt < 8; nt++)
#pragma unroll
        for (int i = 0; i < 4; i++) o[nt][i] = 0.f;

    const int wrow = wid * 16;
    float* Pw = sm + PF0 + wid * (16 * PPAD);
    const int ntiles = 4 * qi + 4;

    for (int jt = 0; jt < ntiles; jt++) {
        const int bi = jt & 1;
        const int k0 = jt * ABK;
        if (jt + 1 < ntiles) {
            issue_kv(jt + 1, bi ^ 1);
            asm volatile("cp.async.wait_group 1;" ::: "memory");
        } else {
            asm volatile("cp.async.wait_group 0;" ::: "memory");
        }
        __syncthreads();

        const float* Kb = sm + KF0 + bi * 2176;
        const float* Vb = sm + VF0 + bi * 2176;

        float acc[4][4];
#pragma unroll
        for (int nt = 0; nt < 4; nt++)
#pragma unroll
            for (int i = 0; i < 4; i++) acc[nt][i] = 0.f;

#pragma unroll
        for (int kb = 0; kb < 8; kb++) {
            uint32_t aq[4];
            aq[0] = __float_as_uint(sm[QF0 + (wrow + g) * APAD + kb * 8 + t4]);
            aq[1] = __float_as_uint(sm[QF0 + (wrow + g + 8) * APAD + kb * 8 + t4]);
            aq[2] = __float_as_uint(sm[QF0 + (wrow + g) * APAD + kb * 8 + t4 + 4]);
            aq[3] = __float_as_uint(sm[QF0 + (wrow + g + 8) * APAD + kb * 8 + t4 + 4]);
#pragma unroll
            for (int nt = 0; nt < 4; nt++) {
                uint32_t bh[2];
                bh[0] = __float_as_uint(Kb[(nt * 8 + g) * APAD + kb * 8 + t4]);
                bh[1] = __float_as_uint(Kb[(nt * 8 + g) * APAD + kb * 8 + t4 + 4]);
                mma_tf32(acc[nt], aq, bh);
            }
        }

        if (jt >= ntiles - 4) {
            const int r0g = q0 + wrow + g;
            const int r1g = r0g + 8;
#pragma unroll
            for (int nt = 0; nt < 4; nt++) {
                const int c = k0 + nt * 8 + t4 * 2;
                if (c > r0g)     acc[nt][0] = -1e30f;
                if (c + 1 > r0g) acc[nt][1] = -1e30f;
                if (c > r1g)     acc[nt][2] = -1e30f;
                if (c + 1 > r1g) acc[nt][3] = -1e30f;
            }
        }

        float mx0 = -1e30f, mx1 = -1e30f;
#pragma unroll
        for (int nt = 0; nt < 4; nt++) {
            mx0 = fmaxf(mx0, fmaxf(acc[nt][0], acc[nt][1]));
            mx1 = fmaxf(mx1, fmaxf(acc[nt][2], acc[nt][3]));
        }
        mx0 = fmaxf(mx0, __shfl_xor_sync(0xffffffffu, mx0, 1));
        mx0 = fmaxf(mx0, __shfl_xor_sync(0xffffffffu, mx0, 2));
        mx1 = fmaxf(mx1, __shfl_xor_sync(0xffffffffu, mx1, 1));
        mx1 = fmaxf(mx1, __shfl_xor_sync(0xffffffffu, mx1, 2));
        const float mn0 = fmaxf(m0, mx0);
        const float mn1 = fmaxf(m1, mx1);
        const float a0 = __expf(m0 - mn0);
        const float a1 = __expf(m1 - mn1);
        m0 = mn0; m1 = mn1;
        float s0 = 0.f, s1 = 0.f;
#pragma unroll
        for (int nt = 0; nt < 4; nt++) {
            acc[nt][0] = __expf(acc[nt][0] - m0); s0 += acc[nt][0];
            acc[nt][1] = __expf(acc[nt][1] - m0); s0 += acc[nt][1];
            acc[nt][2] = __expf(acc[nt][2] - m1); s1 += acc[nt][2];
            acc[nt][3] = __expf(acc[nt][3] - m1); s1 += acc[nt][3];
        }
        s0 += __shfl_xor_sync(0xffffffffu, s0, 1);
        s0 += __shfl_xor_sync(0xffffffffu, s0, 2);
        s1 += __shfl_xor_sync(0xffffffffu, s1, 1);
        s1 += __shfl_xor_sync(0xffffffffu, s1, 2);
        l0 = l0 * a0 + s0;
        l1 = l1 * a1 + s1;

#pragma unroll
        for (int nt = 0; nt < 4; nt++) {
            Pw[g * PPAD + nt * 8 + t4 * 2]           = tf32_rna(acc[nt][0]);
            Pw[g * PPAD + nt * 8 + t4 * 2 + 1]       = tf32_rna(acc[nt][1]);
            Pw[(g + 8) * PPAD + nt * 8 + t4 * 2]     = tf32_rna(acc[nt][2]);
            Pw[(g + 8) * PPAD + nt * 8 + t4 * 2 + 1] = tf32_rna(acc[nt][3]);
        }
        __syncwarp();

#pragma unroll
        for (int nt = 0; nt < 8; nt++) {
            o[nt][0] *= a0; o[nt][1] *= a0;
            o[nt][2] *= a1; o[nt][3] *= a1;
        }

#pragma unroll
        for (int kb = 0; kb < 4; kb++) {
            uint32_t ap[4];
            ap[0] = __float_as_uint(Pw[g * PPAD + kb * 8 + t4]);
            ap[1] = __float_as_uint(Pw[(g + 8) * PPAD + kb * 8 + t4]);
            ap[2] = __float_as_uint(Pw[g * PPAD + kb * 8 + t4 + 4]);
            ap[3] = __float_as_uint(Pw[(g + 8) * PPAD + kb * 8 + t4 + 4]);
#pragma unroll
            for (int nt = 0; nt < 8; nt++) {
                uint32_t bh[2];
                bh[0] = __float_as_uint(Vb[(kb * 8 + t4) * APAD + nt * 8 + g]);
                bh[1] = __float_as_uint(Vb[(kb * 8 + t4 + 4) * APAD + nt * 8 + g]);
                mma_tf32(o[nt], ap, bh);
            }
        }
        __syncwarp();
        __syncthreads();
    }

    const float i0 = 1.f / l0;
    const float i1 = 1.f / l1;
    const int r0g = q0 + wrow + g;
#pragma unroll
    for (int nt = 0; nt < 8; nt++) {
        const int col = h * Dn + nt * 8 + t4 * 2;
        float2 v0, v1;
        v0.x = o[nt][0] * i0; v0.y = o[nt][1] * i0;
        v1.x = o[nt][2] * i1; v1.y = o[nt][3] * i1;
        *(float2*)(out + ((size_t)b * Sn + r0g) * En + col) = v0;
        *(float2*)(out + ((size_t)b * Sn + r0g + 8) * En + col) = v1;
    }
}

// ----------------------------------------------------------------------------
extern "C" void kernel_launch(void* const* d_in, const int* in_sizes, int n_in,
                              void* d_out, int out_size)
{
    const float* x     = (const float*)d_in[0];
    const float* w_in  = (const float*)d_in[1];
    const float* b_in  = (const float*)d_in[2];
    const float* w_out = (const float*)d_in[3];
    const float* b_out = (const float*)d_in[4];
    float* out = (float*)d_out;

    float *qkv, *attn;
    uint4 *xh, *xl, *ah, *al, *wih, *wil, *woh, *wol;
    cudaGetSymbolAddress((void**)&qkv, g_qkv);
    cudaGetSymbolAddress((void**)&attn, g_attn);
    cudaGetSymbolAddress((void**)&xh, g_xh);
    cudaGetSymbolAddress((void**)&xl, g_xl);
    cudaGetSymbolAddress((void**)&ah, g_ah);
    cudaGetSymbolAddress((void**)&al, g_al);
    cudaGetSymbolAddress((void**)&wih, g_wih);
    cudaGetSymbolAddress((void**)&wil, g_wil);
    cudaGetSymbolAddress((void**)&woh, g_woh);
    cudaGetSymbolAddress((void**)&wol, g_wol);

    static bool attr_set = false;
    if (!attr_set) {
        cudaFuncSetAttribute(gemm_pre, cudaFuncAttributeMaxDynamicSharedMemorySize,
                             GEMM_SMEM);
        cudaFuncSetAttribute(attn_mma, cudaFuncAttributeMaxDynamicSharedMemorySize,
                             ATTN_SMEM);
        attr_set = true;
    }

    // 0) Pre-split operands into fragment-major bf16 hi/lo
    prep_a<<<4096, 256>>>(x, xh, xl, En);          // 8192x1024
    prep_b<<<1536, 256>>>(w_in, wih, wil, En);     // 3072x1024

    // 1) QKV projection; K/V columns (tiles >= 8) pre-rounded to tf32
    {
        dim3 grid(24, 64);
        gemm_pre<<<grid, 256, GEMM_SMEM>>>(xh, xl, wih, wil, b_in, qkv,
                                           3 * En, En / 32, 8);
    }

    // 2) Causal flash attention (tf32, cp.async double-buffered K/V)
    {
        dim3 grid(Sn / ABQ, Hn, Bn);
        attn_mma<<<grid, 256, ATTN_SMEM>>>(qkv, attn);
    }

    // 3) Output projection
    prep_a<<<4096, 256>>>(attn, ah, al, En);       // 8192x1024
    prep_b<<<512, 256>>>(w_out, woh, wol, En);     // 1024x1024
    {
        dim3 grid(8, 64);
        gemm_pre<<<grid, 256, GEMM_SMEM>>>(ah, al, woh, wol, b_out, out,
                                           En, En / 32, 1 << 30);
    }
}

// round 11
// speedup vs baseline: 1.2377x; 1.0186x over previous
#include <cuda_runtime.h>
#include <cuda_bf16.h>
#include <cstdint>
#include <cstddef>

// Problem constants
static constexpr int Bn = 4;
static constexpr int Sn = 2048;
static constexpr int En = 1024;
static constexpr int Hn = 16;
static constexpr int Dn = 64;

// Scratch (device globals; no cudaMalloc allowed)
__device__ float g_qkv[(size_t)Bn * Sn * 3 * En];   // [B,S,3E]
__device__ float g_attn[(size_t)Bn * Sn * En];      // [B,S,E]

// Pre-split bf16 hi/lo operand tiles (fragment-major layout)
__device__ uint4 g_xh[1048576], g_xl[1048576];      // x:    [64][32][4096 bf16]
__device__ uint4 g_ah[1048576], g_al[1048576];      // attn: [64][32][4096 bf16]
__device__ uint4 g_wih[393216], g_wil[393216];      // w_in: [24][32][4096 bf16]
__device__ uint4 g_woh[131072], g_wol[131072];      // w_out:[ 8][32][4096 bf16]

__device__ __forceinline__ float tf32_rna(float x) {
    uint32_t u;
    asm("cvt.rna.tf32.f32 %0, %1;" : "=r"(u) : "f"(x));
    return __uint_as_float(u);
}

__device__ __forceinline__ void mma_tf32(float* c, const uint32_t* a, const uint32_t* b) {
    asm volatile(
        "mma.sync.aligned.m16n8k8.row.col.f32.tf32.tf32.f32 "
        "{%0,%1,%2,%3}, {%4,%5,%6,%7}, {%8,%9}, {%0,%1,%2,%3};"
        : "+f"(c[0]), "+f"(c[1]), "+f"(c[2]), "+f"(c[3])
        : "r"(a[0]), "r"(a[1]), "r"(a[2]), "r"(a[3]), "r"(b[0]), "r"(b[1]));
}

__device__ __forceinline__ void mma_bf16(float* c, const uint32_t* a, const uint32_t* b) {
    asm volatile(
        "mma.sync.aligned.m16n8k16.row.col.f32.bf16.bf16.f32 "
        "{%0,%1,%2,%3}, {%4,%5,%6,%7}, {%8,%9}, {%0,%1,%2,%3};"
        : "+f"(c[0]), "+f"(c[1]), "+f"(c[2]), "+f"(c[3])
        : "r"(a[0]), "r"(a[1]), "r"(a[2]), "r"(a[3]), "r"(b[0]), "r"(b[1]));
}

__device__ __forceinline__ void split_pack_bf16(float x0, float x1,
                                                uint32_t& hi, uint32_t& lo) {
    __nv_bfloat162 h = __floats2bfloat162_rn(x0, x1);
    float f0 = __bfloat162float(h.x);
    float f1 = __bfloat162float(h.y);
    __nv_bfloat162 l = __floats2bfloat162_rn(x0 - f0, x1 - f1);
    hi = *(uint32_t*)&h;
    lo = *(uint32_t*)&l;
}

__device__ __forceinline__ void cp16(uint32_t dst, const void* src) {
    asm volatile("cp.async.ca.shared.global [%0], [%1], 16;"
                 :: "r"(dst), "l"(src) : "memory");
}

#define MBARRIER_INIT(addr, count) \
    asm volatile("mbarrier.init.shared.b64 [%0], %1;" :: "r"((uint32_t)(addr)), "r"((uint32_t)(count)) : "memory")
#define MBARRIER_ARRIVE(addr) \
    asm volatile("mbarrier.arrive.shared.b64 _, [%0];" :: "r"((uint32_t)(addr)) : "memory")
#define MBARRIER_WAIT_PARITY(addr, parity) do { \
    uint32_t _m = (uint32_t)(addr); uint32_t _p = (uint32_t)(parity); uint32_t _d; \
    asm volatile("{\n\t.reg .pred p;\n\t" \
        "mbarrier.try_wait.parity.acquire.cta.shared::cta.b64 p, [%1], %2;\n\t" \
        "selp.b32 %0, 1, 0, p;\n\t}" : "=r"(_d) : "r"(_m), "r"(_p) : "memory"); \
    if (!_d) { \
        asm volatile("{\n\t.reg .pred P1;\n\t" \
            "WL_%=:\n\t" \
            "mbarrier.try_wait.parity.acquire.cta.shared::cta.b64 P1, [%0], %1, 0x989680;\n\t" \
            "@P1 bra.uni WD_%=;\n\tbra.uni WL_%=;\n\tWD_%=:\n\t}" \
            :: "r"(_m), "r"(_p) : "memory"); \
    } } while (0)

// ============================================================================
// Prep kernels (R10 proven): split fp32 -> bf16 hi/lo, fragment-major layout.
// ============================================================================
__global__ __launch_bounds__(256) void prep_a(
    const float* __restrict__ A, uint4* __restrict__ H, uint4* __restrict__ L, int K)
{
    const size_t o = (size_t)blockIdx.x * 256 + threadIdx.x;
    const int u4 = (int)(o & 511);
    const int tile = (int)(o >> 9);
    const int kT = K >> 5;
    const int mt = tile / kT, kt = tile % kT;
    const int blkPair = u4 >> 5;
    const int m16 = blkPair >> 1, kblk = blkPair & 1;
    const int rem = u4 & 31;
    const int g = rem >> 2, t4 = rem & 3;
    const int r0 = mt * 128 + m16 * 16 + g;
    const int kb = kt * 32 + kblk * 16 + t4 * 2;
    const float* p0 = A + (size_t)r0 * K + kb;
    const float* p1 = p0 + (size_t)8 * K;
    const float2 a00 = *(const float2*)p0;
    const float2 a10 = *(const float2*)p1;
    const float2 a01 = *(const float2*)(p0 + 8);
    const float2 a11 = *(const float2*)(p1 + 8);
    uint4 hv, lv;
    split_pack_bf16(a00.x, a00.y, hv.x, lv.x);
    split_pack_bf16(a10.x, a10.y, hv.y, lv.y);
    split_pack_bf16(a01.x, a01.y, hv.z, lv.z);
    split_pack_bf16(a11.x, a11.y, hv.w, lv.w);
    H[o] = hv; L[o] = lv;
}

__global__ __launch_bounds__(256) void prep_b(
    const float* __restrict__ B, uint4* __restrict__ H, uint4* __restrict__ L, int K)
{
    const size_t o = (size_t)blockIdx.x * 256 + threadIdx.x;
    const int u4 = (int)(o & 511);
    const int tile = (int)(o >> 9);
    const int kT = K >> 5;
    const int nt = tile / kT, kt = tile % kT;
    const int blkPair = u4 >> 4;
    const int nblk = blkPair >> 1, kblk = blkPair & 1;
    const int rem = u4 & 15;
    const int g = rem >> 1, j = rem & 1;
    const int n = nt * 128 + nblk * 8 + g;
    const int kb = kt * 32 + kblk * 16 + j * 4;
    const float4 p = *(const float4*)(B + (size_t)n * K + kb);
    const float4 q = *(const float4*)(B + (size_t)n * K + kb + 8);
    uint4 hv, lv;
    split_pack_bf16(p.x, p.y, hv.x, lv.x);
    split_pack_bf16(q.x, q.y, hv.y, lv.y);
    split_pack_bf16(p.z, p.w, hv.z, lv.z);
    split_pack_bf16(q.z, q.w, hv.w, lv.w);
    H[o] = hv; L[o] = lv;
}

// ============================================================================
// 3xBF16 tensor-core GEMM on pre-split fragment-major operands.
// Now with ONE __syncthreads per k-iter (issue moved after the barrier).
// ============================================================================
static constexpr int STAGE_E = 16384;                 // bf16 per stage (32 KB)
static constexpr int GEMM_SMEM = 3 * STAGE_E * 2;     // 98304 bytes

__global__ __launch_bounds__(256, 2) void gemm_pre(
    const uint4* __restrict__ AH, const uint4* __restrict__ AL,
    const uint4* __restrict__ BH, const uint4* __restrict__ BL,
    const float* __restrict__ bias, float* __restrict__ C,
    int N, int kT, int roundFromTile)
{
    extern __shared__ uint16_t smu[];
    const int tid = threadIdx.x;
    const int wid = tid >> 5;
    const int lane = tid & 31;
    const int g = lane >> 2;
    const int t4 = lane & 3;
    const int wm = wid >> 1;
    const int wn = wid & 1;
    const int mt = blockIdx.y;
    const int nt = blockIdx.x;
    const uint32_t smem_base = (uint32_t)__cvta_generic_to_shared(smu);

    const size_t atile = (size_t)mt * kT;
    const size_t btile = (size_t)nt * kT;

    auto issue = [&](int j, int st) {
        const uint32_t dst0 = smem_base + st * 32768;
#pragma unroll
        for (int s = 0; s < 8; s++) {
            const int arr = s >> 1;
            const int off = tid + (s & 1) * 256;
            const uint4* bp = (arr == 0) ? AH : (arr == 1) ? AL
                             : (arr == 2) ? BH : BL;
            const size_t tb = (arr < 2) ? atile : btile;
            cp16(dst0 + arr * 8192 + off * 16, bp + (tb + j) * 512 + off);
        }
        asm volatile("cp.async.commit_group;" ::: "memory");
    };

    float acc[2][8][4];
#pragma unroll
    for (int mtl = 0; mtl < 2; mtl++)
#pragma unroll
        for (int ntl = 0; ntl < 8; ntl++)
#pragma unroll
            for (int i = 0; i < 4; i++) acc[mtl][ntl][i] = 0.f;

    issue(0, 0);
    issue(1, 1);

    for (int j = 0; j < kT; j++) {
        if (j + 1 < kT) {
            asm volatile("cp.async.wait_group 1;" ::: "memory");
        } else {
            asm volatile("cp.async.wait_group 0;" ::: "memory");
        }
        __syncthreads();
        if (j + 2 < kT) issue(j + 2, (j + 2) % 3);

        const uint16_t* stg = smu + (j % 3) * STAGE_E;
#pragma unroll
        for (int kblk = 0; kblk < 2; kblk++) {
            uint4 ahi[2], alo[2];
#pragma unroll
            for (int mtl = 0; mtl < 2; mtl++) {
                const int mblk = wm * 2 + mtl;
                const int base = (mblk * 2 + kblk) * 256 + g * 32 + t4 * 8;
                ahi[mtl] = *(const uint4*)(stg + base);
                alo[mtl] = *(const uint4*)(stg + 4096 + base);
            }
#pragma unroll
            for (int ntl = 0; ntl < 8; ntl++) {
                const int nblk = wn * 8 + ntl;
                const int bbase = (nblk * 2 + kblk) * 128 + g * 16 + t4 * 4;
                uint2 bh = *(const uint2*)(stg + 8192 + bbase);
                uint2 bl = *(const uint2*)(stg + 12288 + bbase);
#pragma unroll
                for (int mtl = 0; mtl < 2; mtl++) {
                    mma_bf16(acc[mtl][ntl], (const uint32_t*)&ahi[mtl], (const uint32_t*)&bh);
                    mma_bf16(acc[mtl][ntl], (const uint32_t*)&ahi[mtl], (const uint32_t*)&bl);
                    mma_bf16(acc[mtl][ntl], (const uint32_t*)&alo[mtl], (const uint32_t*)&bh);
                }
            }
        }
    }

    const bool roundT = (nt >= roundFromTile);
    const int bm = mt * 128;
    const int bn = nt * 128;
#pragma unroll
    for (int mtl = 0; mtl < 2; mtl++) {
        const int r0 = bm + wm * 32 + mtl * 16 + g;
#pragma unroll
        for (int ntl = 0; ntl < 8; ntl++) {
            const int c0 = bn + wn * 64 + ntl * 8 + t4 * 2;
            const float b0 = bias[c0];
            const float b1 = bias[c0 + 1];
            float2 v0, v1;
            v0.x = acc[mtl][ntl][0] + b0; v0.y = acc[mtl][ntl][1] + b1;
            v1.x = acc[mtl][ntl][2] + b0; v1.y = acc[mtl][ntl][3] + b1;
            if (roundT) {
                v0.x = tf32_rna(v0.x); v0.y = tf32_rna(v0.y);
                v1.x = tf32_rna(v1.x); v1.y = tf32_rna(v1.y);
            }
            *(float2*)(C + (size_t)r0 * N + c0) = v0;
            *(float2*)(C + (size_t)(r0 + 8) * N + c0) = v1;
        }
    }
}

// ============================================================================
// Flash attention: tf32 mma.sync, producer-warp mbarrier pipeline.
// Block = 288 threads: warps 0-7 compute (16 q-rows each), warp 8 = producer.
// 3-stage K/V ring; zero block barriers in the tile loop.
// K/V in g_qkv pre-rounded to tf32 -> cp.async raw copy is exact.
//
// smem (floats): [0..31] mbarriers (full[3]@0B, empty[3]@24B)
//   QF0=32 (128x68), KV0=8736 (3 stages x (K 2176 + V 2176)), PF0=21792
// ============================================================================
static constexpr int ABQ = 128, ABK = 32, APAD = 68, PPAD = 36;
static constexpr int QF0 = 32;
static constexpr int KV0 = QF0 + ABQ * APAD;            // 8736
static constexpr int PF0 = KV0 + 3 * 4352;              // 21792
static constexpr int ATTN_SMEM = (PF0 + 8 * 16 * PPAD) * 4;  // 105600 B

__global__ __launch_bounds__(288, 2) void attn_mma(
    const float* __restrict__ qkv, float* __restrict__ out)
{
    extern __shared__ float sm[];
    const int tid = threadIdx.x;
    const int wid = tid >> 5;
    const int lane = tid & 31;
    const int g = lane >> 2;
    const int t4 = lane & 3;
    const int qi = gridDim.x - 1 - blockIdx.x;
    const int h = blockIdx.y;
    const int b = blockIdx.z;
    const int q0 = qi * ABQ;
    const size_t rs = (size_t)3 * En;
    const float* qbase = qkv + (size_t)b * Sn * rs + (size_t)h * Dn;
    const float* kbase = qbase + En;
    const float* vbase = qbase + 2 * En;
    const uint32_t smem_base = (uint32_t)__cvta_generic_to_shared(sm);
    const int ntiles = 4 * qi + 4;

    if (tid == 0) {
#pragma unroll
        for (int s = 0; s < 3; s++) {
            MBARRIER_INIT(smem_base + s * 8, 32);        // full[s]: 32 producer lanes
            MBARRIER_INIT(smem_base + 24 + s * 8, 8);    // empty[s]: 8 compute warps
        }
    }

    // Q tile -> smem (scaled, rna-truncated); compute threads only
    if (tid < 256) {
        for (int i = tid; i < ABQ * 16; i += 256) {
            const int row = i >> 4, c4 = (i & 15) * 4;
            float4 v = *(const float4*)(qbase + (size_t)(q0 + row) * rs + c4);
            float4 hi;
            hi.x = tf32_rna(v.x * 0.125f);
            hi.y = tf32_rna(v.y * 0.125f);
            hi.z = tf32_rna(v.z * 0.125f);
            hi.w = tf32_rna(v.w * 0.125f);
            *(float4*)&sm[QF0 + row * APAD + c4] = hi;
        }
    }
    __syncthreads();   // mbarrier init + Q visible to all

    if (tid >= 256) {
        // -------- producer warp --------
        for (int j = 0; j < ntiles; j++) {
            const int q3 = j / 3;
            const int s = j - 3 * q3;
            if (j >= 3) {
                MBARRIER_WAIT_PARITY(smem_base + 24 + s * 8, (q3 - 1) & 1);
            }
            const int k0 = j * ABK;
            const int base = KV0 + s * 4352;
#pragma unroll
            for (int c = 0; c < 32; c++) {
                const int i = c * 32 + lane;
                const int isV = i >> 9;
                const int ii = i & 511;
                const int row = ii >> 4, q = ii & 15;
                const float* src = (isV ? vbase : kbase) + (size_t)(k0 + row) * rs + q * 4;
                const int dstf = base + isV * 2176 + row * APAD + q * 4;
                cp16(smem_base + dstf * 4, src);
            }
            asm volatile("cp.async.commit_group;" ::: "memory");
            if (j >= 2) {
                asm volatile("cp.async.wait_group 2;" ::: "memory");
                MBARRIER_ARRIVE(smem_base + ((j - 2) % 3) * 8);
            }
        }
        asm volatile("cp.async.wait_group 1;" ::: "memory");
        MBARRIER_ARRIVE(smem_base + ((ntiles - 2) % 3) * 8);
        asm volatile("cp.async.wait_group 0;" ::: "memory");
        MBARRIER_ARRIVE(smem_base + ((ntiles - 1) % 3) * 8);
        return;
    }

    // -------- compute warps --------
    float m0 = -1e30f, m1 = -1e30f, l0 = 0.f, l1 = 0.f;
    float o[8][4];
#pragma unroll
    for (int nt = 0; nt < 8; nt++)
#pragma unroll
        for (int i = 0; i < 4; i++) o[nt][i] = 0.f;

    const int wrow = wid * 16;
    float* Pw = sm + PF0 + wid * (16 * PPAD);

    for (int jt = 0; jt < ntiles; jt++) {
        const int q3 = jt / 3;
        const int s = jt - 3 * q3;
        const int k0 = jt * ABK;
        MBARRIER_WAIT_PARITY(smem_base + s * 8, q3 & 1);

        const float* Kb = sm + KV0 + s * 4352;
        const float* Vb = Kb + 2176;

        // ---- S = (Q/8) @ K^T ----
        float acc[4][4];
#pragma unroll
        for (int nt = 0; nt < 4; nt++)
#pragma unroll
            for (int i = 0; i < 4; i++) acc[nt][i] = 0.f;

#pragma unroll
        for (int kb = 0; kb < 8; kb++) {
            uint32_t aq[4];
            aq[0] = __float_as_uint(sm[QF0 + (wrow + g) * APAD + kb * 8 + t4]);
            aq[1] = __float_as_uint(sm[QF0 + (wrow + g + 8) * APAD + kb * 8 + t4]);
            aq[2] = __float_as_uint(sm[QF0 + (wrow + g) * APAD + kb * 8 + t4 + 4]);
            aq[3] = __float_as_uint(sm[QF0 + (wrow + g + 8) * APAD + kb * 8 + t4 + 4]);
#pragma unroll
            for (int nt = 0; nt < 4; nt++) {
                uint32_t bh[2];
                bh[0] = __float_as_uint(Kb[(nt * 8 + g) * APAD + kb * 8 + t4]);
                bh[1] = __float_as_uint(Kb[(nt * 8 + g) * APAD + kb * 8 + t4 + 4]);
                mma_tf32(acc[nt], aq, bh);
            }
        }

        // ---- causal mask (4 diagonal-overlapping tiles) ----
        if (jt >= ntiles - 4) {
            const int r0g = q0 + wrow + g;
            const int r1g = r0g + 8;
#pragma unroll
            for (int nt = 0; nt < 4; nt++) {
                const int c = k0 + nt * 8 + t4 * 2;
                if (c > r0g)     acc[nt][0] = -1e30f;
                if (c + 1 > r0g) acc[nt][1] = -1e30f;
                if (c > r1g)     acc[nt][2] = -1e30f;
                if (c + 1 > r1g) acc[nt][3] = -1e30f;
            }
        }

        // ---- online softmax ----
        float mx0 = -1e30f, mx1 = -1e30f;
#pragma unroll
        for (int nt = 0; nt < 4; nt++) {
            mx0 = fmaxf(mx0, fmaxf(acc[nt][0], acc[nt][1]));
            mx1 = fmaxf(mx1, fmaxf(acc[nt][2], acc[nt][3]));
        }
        mx0 = fmaxf(mx0, __shfl_xor_sync(0xffffffffu, mx0, 1));
        mx0 = fmaxf(mx0, __shfl_xor_sync(0xffffffffu, mx0, 2));
        mx1 = fmaxf(mx1, __shfl_xor_sync(0xffffffffu, mx1, 1));
        mx1 = fmaxf(mx1, __shfl_xor_sync(0xffffffffu, mx1, 2));
        const float mn0 = fmaxf(m0, mx0);
        const float mn1 = fmaxf(m1, mx1);
        const float a0 = __expf(m0 - mn0);
        const float a1 = __expf(m1 - mn1);
        m0 = mn0; m1 = mn1;
        float s0 = 0.f, s1 = 0.f;
#pragma unroll
        for (int nt = 0; nt < 4; nt++) {
            acc[nt][0] = __expf(acc[nt][0] - m0); s0 += acc[nt][0];
            acc[nt][1] = __expf(acc[nt][1] - m0); s0 += acc[nt][1];
            acc[nt][2] = __expf(acc[nt][2] - m1); s1 += acc[nt][2];
            acc[nt][3] = __expf(acc[nt][3] - m1); s1 += acc[nt][3];
        }
        s0 += __shfl_xor_sync(0xffffffffu, s0, 1);
        s0 += __shfl_xor_sync(0xffffffffu, s0, 2);
        s1 += __shfl_xor_sync(0xffffffffu, s1, 1);
        s1 += __shfl_xor_sync(0xffffffffu, s1, 2);
        l0 = l0 * a0 + s0;
        l1 = l1 * a1 + s1;

        // ---- P -> warp-private smem ----
#pragma unroll
        for (int nt = 0; nt < 4; nt++) {
            Pw[g * PPAD + nt * 8 + t4 * 2]           = tf32_rna(acc[nt][0]);
            Pw[g * PPAD + nt * 8 + t4 * 2 + 1]       = tf32_rna(acc[nt][1]);
            Pw[(g + 8) * PPAD + nt * 8 + t4 * 2]     = tf32_rna(acc[nt][2]);
            Pw[(g + 8) * PPAD + nt * 8 + t4 * 2 + 1] = tf32_rna(acc[nt][3]);
        }
        __syncwarp();

        // ---- rescale O ----
#pragma unroll
        for (int nt = 0; nt < 8; nt++) {
            o[nt][0] *= a0; o[nt][1] *= a0;
            o[nt][2] *= a1; o[nt][3] *= a1;
        }

        // ---- O += P @ V ----
#pragma unroll
        for (int kb = 0; kb < 4; kb++) {
            uint32_t ap[4];
            ap[0] = __float_as_uint(Pw[g * PPAD + kb * 8 + t4]);
            ap[1] = __float_as_uint(Pw[(g + 8) * PPAD + kb * 8 + t4]);
            ap[2] = __float_as_uint(Pw[g * PPAD + kb * 8 + t4 + 4]);
            ap[3] = __float_as_uint(Pw[(g + 8) * PPAD + kb * 8 + t4 + 4]);
#pragma unroll
            for (int nt = 0; nt < 8; nt++) {
                uint32_t bh[2];
                bh[0] = __float_as_uint(Vb[(kb * 8 + t4) * APAD + nt * 8 + g]);
                bh[1] = __float_as_uint(Vb[(kb * 8 + t4 + 4) * APAD + nt * 8 + g]);
                mma_tf32(o[nt], ap, bh);
            }
        }
        __syncwarp();
        if (lane == 0) MBARRIER_ARRIVE(smem_base + 24 + s * 8);
    }

    // ---- normalize + store ----
    const float i0 = 1.f / l0;
    const float i1 = 1.f / l1;
    const int r0g = q0 + wrow + g;
#pragma unroll
    for (int nt = 0; nt < 8; nt++) {
        const int col = h * Dn + nt * 8 + t4 * 2;
        float2 v0, v1;
        v0.x = o[nt][0] * i0; v0.y = o[nt][1] * i0;
        v1.x = o[nt][2] * i1; v1.y = o[nt][3] * i1;
        *(float2*)(out + ((size_t)b * Sn + r0g) * En + col) = v0;
        *(float2*)(out + ((size_t)b * Sn + r0g + 8) * En + col) = v1;
    }
}

// ----------------------------------------------------------------------------
extern "C" void kernel_launch(void* const* d_in, const int* in_sizes, int n_in,
                              void* d_out, int out_size)
{
    const float* x     = (const float*)d_in[0];
    const float* w_in  = (const float*)d_in[1];
    const float* b_in  = (const float*)d_in[2];
    const float* w_out = (const float*)d_in[3];
    const float* b_out = (const float*)d_in[4];
    float* out = (float*)d_out;

    float *qkv, *attn;
    uint4 *xh, *xl, *ah, *al, *wih, *wil, *woh, *wol;
    cudaGetSymbolAddress((void**)&qkv, g_qkv);
    cudaGetSymbolAddress((void**)&attn, g_attn);
    cudaGetSymbolAddress((void**)&xh, g_xh);
    cudaGetSymbolAddress((void**)&xl, g_xl);
    cudaGetSymbolAddress((void**)&ah, g_ah);
    cudaGetSymbolAddress((void**)&al, g_al);
    cudaGetSymbolAddress((void**)&wih, g_wih);
    cudaGetSymbolAddress((void**)&wil, g_wil);
    cudaGetSymbolAddress((void**)&woh, g_woh);
    cudaGetSymbolAddress((void**)&wol, g_wol);

    static bool attr_set = false;
    if (!attr_set) {
        cudaFuncSetAttribute(gemm_pre, cudaFuncAttributeMaxDynamicSharedMemorySize,
                             GEMM_SMEM);
        cudaFuncSetAttribute(attn_mma, cudaFuncAttributeMaxDynamicSharedMemorySize,
                             ATTN_SMEM);
        attr_set = true;
    }

    // 0) Pre-split operands into fragment-major bf16 hi/lo
    prep_a<<<4096, 256>>>(x, xh, xl, En);
    prep_b<<<1536, 256>>>(w_in, wih, wil, En);

    // 1) QKV projection; K/V columns (tiles >= 8) pre-rounded to tf32
    {
        dim3 grid(24, 64);
        gemm_pre<<<grid, 256, GEMM_SMEM>>>(xh, xl, wih, wil, b_in, qkv,
                                           3 * En, En / 32, 8);
    }

    // 2) Causal flash attention (tf32, producer-warp mbarrier pipeline)
    {
        dim3 grid(Sn / ABQ, Hn, Bn);
        attn_mma<<<grid, 288, ATTN_SMEM>>>(qkv, attn);
    }

    // 3) Output projection
    prep_a<<<4096, 256>>>(attn, ah, al, En);
    prep_b<<<512, 256>>>(w_out, woh, wol, En);
    {
        dim3 grid(8, 64);
        gemm_pre<<<grid, 256, GEMM_SMEM>>>(ah, al, woh, wol, b_out, out,
                                           En, En / 32, 1 << 30);
    }
}

// round 12
// speedup vs baseline: 1.3530x; 1.0931x over previous
#include <cuda_runtime.h>
#include <cuda_bf16.h>
#include <cstdint>
#include <cstddef>

// Problem constants
static constexpr int Bn = 4;
static constexpr int Sn = 2048;
static constexpr int En = 1024;
static constexpr int Hn = 16;
static constexpr int Dn = 64;

// Scratch (device globals; no cudaMalloc allowed)
__device__ float g_qkv[(size_t)Bn * Sn * 3 * En];   // [B,S,3E]
__device__ float g_attn[(size_t)Bn * Sn * En];      // [B,S,E]

// Pre-split bf16 hi/lo operand tiles (fragment-major layout)
__device__ uint4 g_xh[1048576], g_xl[1048576];      // x:    [64][32][4096 bf16]
__device__ uint4 g_ah[1048576], g_al[1048576];      // attn: [64][32][4096 bf16]
__device__ uint4 g_wih[393216], g_wil[393216];      // w_in: [24][32][4096 bf16]
__device__ uint4 g_woh[131072], g_wol[131072];      // w_out:[ 8][32][4096 bf16]

__device__ __forceinline__ float tf32_rna(float x) {
    uint32_t u;
    asm("cvt.rna.tf32.f32 %0, %1;" : "=r"(u) : "f"(x));
    return __uint_as_float(u);
}

__device__ __forceinline__ void mma_tf32(float* c, const uint32_t* a, const uint32_t* b) {
    asm volatile(
        "mma.sync.aligned.m16n8k8.row.col.f32.tf32.tf32.f32 "
        "{%0,%1,%2,%3}, {%4,%5,%6,%7}, {%8,%9}, {%0,%1,%2,%3};"
        : "+f"(c[0]), "+f"(c[1]), "+f"(c[2]), "+f"(c[3])
        : "r"(a[0]), "r"(a[1]), "r"(a[2]), "r"(a[3]), "r"(b[0]), "r"(b[1]));
}

__device__ __forceinline__ void mma_bf16(float* c, const uint32_t* a, const uint32_t* b) {
    asm volatile(
        "mma.sync.aligned.m16n8k16.row.col.f32.bf16.bf16.f32 "
        "{%0,%1,%2,%3}, {%4,%5,%6,%7}, {%8,%9}, {%0,%1,%2,%3};"
        : "+f"(c[0]), "+f"(c[1]), "+f"(c[2]), "+f"(c[3])
        : "r"(a[0]), "r"(a[1]), "r"(a[2]), "r"(a[3]), "r"(b[0]), "r"(b[1]));
}

__device__ __forceinline__ void split_pack_bf16(float x0, float x1,
                                                uint32_t& hi, uint32_t& lo) {
    __nv_bfloat162 h = __floats2bfloat162_rn(x0, x1);
    float f0 = __bfloat162float(h.x);
    float f1 = __bfloat162float(h.y);
    __nv_bfloat162 l = __floats2bfloat162_rn(x0 - f0, x1 - f1);
    hi = *(uint32_t*)&h;
    lo = *(uint32_t*)&l;
}

__device__ __forceinline__ void cp16(uint32_t dst, const void* src) {
    asm volatile("cp.async.ca.shared.global [%0], [%1], 16;"
                 :: "r"(dst), "l"(src) : "memory");
}

#define MBARRIER_INIT(addr, count) \
    asm volatile("mbarrier.init.shared.b64 [%0], %1;" :: "r"((uint32_t)(addr)), "r"((uint32_t)(count)) : "memory")
#define MBARRIER_ARRIVE(addr) \
    asm volatile("mbarrier.arrive.shared.b64 _, [%0];" :: "r"((uint32_t)(addr)) : "memory")
#define MBARRIER_WAIT_PARITY(addr, parity) do { \
    uint32_t _m = (uint32_t)(addr); uint32_t _p = (uint32_t)(parity); uint32_t _d; \
    asm volatile("{\n\t.reg .pred p;\n\t" \
        "mbarrier.try_wait.parity.acquire.cta.shared::cta.b64 p, [%1], %2;\n\t" \
        "selp.b32 %0, 1, 0, p;\n\t}" : "=r"(_d) : "r"(_m), "r"(_p) : "memory"); \
    if (!_d) { \
        asm volatile("{\n\t.reg .pred P1;\n\t" \
            "WL_%=:\n\t" \
            "mbarrier.try_wait.parity.acquire.cta.shared::cta.b64 P1, [%0], %1, 0x989680;\n\t" \
            "@P1 bra.uni WD_%=;\n\tbra.uni WL_%=;\n\tWD_%=:\n\t}" \
            :: "r"(_m), "r"(_p) : "memory"); \
    } } while (0)

// ============================================================================
// Prep kernels (R10 proven): split fp32 -> bf16 hi/lo, fragment-major layout.
// ============================================================================
__global__ __launch_bounds__(256) void prep_a(
    const float* __restrict__ A, uint4* __restrict__ H, uint4* __restrict__ L, int K)
{
    const size_t o = (size_t)blockIdx.x * 256 + threadIdx.x;
    const int u4 = (int)(o & 511);
    const int tile = (int)(o >> 9);
    const int kT = K >> 5;
    const int mt = tile / kT, kt = tile % kT;
    const int blkPair = u4 >> 5;
    const int m16 = blkPair >> 1, kblk = blkPair & 1;
    const int rem = u4 & 31;
    const int g = rem >> 2, t4 = rem & 3;
    const int r0 = mt * 128 + m16 * 16 + g;
    const int kb = kt * 32 + kblk * 16 + t4 * 2;
    const float* p0 = A + (size_t)r0 * K + kb;
    const float* p1 = p0 + (size_t)8 * K;
    const float2 a00 = *(const float2*)p0;
    const float2 a10 = *(const float2*)p1;
    const float2 a01 = *(const float2*)(p0 + 8);
    const float2 a11 = *(const float2*)(p1 + 8);
    uint4 hv, lv;
    split_pack_bf16(a00.x, a00.y, hv.x, lv.x);
    split_pack_bf16(a10.x, a10.y, hv.y, lv.y);
    split_pack_bf16(a01.x, a01.y, hv.z, lv.z);
    split_pack_bf16(a11.x, a11.y, hv.w, lv.w);
    H[o] = hv; L[o] = lv;
}

__global__ __launch_bounds__(256) void prep_b(
    const float* __restrict__ B, uint4* __restrict__ H, uint4* __restrict__ L, int K)
{
    const size_t o = (size_t)blockIdx.x * 256 + threadIdx.x;
    const int u4 = (int)(o & 511);
    const int tile = (int)(o >> 9);
    const int kT = K >> 5;
    const int nt = tile / kT, kt = tile % kT;
    const int blkPair = u4 >> 4;
    const int nblk = blkPair >> 1, kblk = blkPair & 1;
    const int rem = u4 & 15;
    const int g = rem >> 1, j = rem & 1;
    const int n = nt * 128 + nblk * 8 + g;
    const int kb = kt * 32 + kblk * 16 + j * 4;
    const float4 p = *(const float4*)(B + (size_t)n * K + kb);
    const float4 q = *(const float4*)(B + (size_t)n * K + kb + 8);
    uint4 hv, lv;
    split_pack_bf16(p.x, p.y, hv.x, lv.x);
    split_pack_bf16(q.x, q.y, hv.y, lv.y);
    split_pack_bf16(p.z, p.w, hv.z, lv.z);
    split_pack_bf16(q.z, q.w, hv.w, lv.w);
    H[o] = hv; L[o] = lv;
}

// ============================================================================
// 3xBF16 tensor-core GEMM on pre-split fragment-major operands (R11 proven).
// ============================================================================
static constexpr int STAGE_E = 16384;                 // bf16 per stage (32 KB)
static constexpr int GEMM_SMEM = 3 * STAGE_E * 2;     // 98304 bytes

__global__ __launch_bounds__(256, 2) void gemm_pre(
    const uint4* __restrict__ AH, const uint4* __restrict__ AL,
    const uint4* __restrict__ BH, const uint4* __restrict__ BL,
    const float* __restrict__ bias, float* __restrict__ C,
    int N, int kT, int roundFromTile)
{
    extern __shared__ uint16_t smu[];
    const int tid = threadIdx.x;
    const int wid = tid >> 5;
    const int lane = tid & 31;
    const int g = lane >> 2;
    const int t4 = lane & 3;
    const int wm = wid >> 1;
    const int wn = wid & 1;
    const int mt = blockIdx.y;
    const int nt = blockIdx.x;
    const uint32_t smem_base = (uint32_t)__cvta_generic_to_shared(smu);

    const size_t atile = (size_t)mt * kT;
    const size_t btile = (size_t)nt * kT;

    auto issue = [&](int j, int st) {
        const uint32_t dst0 = smem_base + st * 32768;
#pragma unroll
        for (int s = 0; s < 8; s++) {
            const int arr = s >> 1;
            const int off = tid + (s & 1) * 256;
            const uint4* bp = (arr == 0) ? AH : (arr == 1) ? AL
                             : (arr == 2) ? BH : BL;
            const size_t tb = (arr < 2) ? atile : btile;
            cp16(dst0 + arr * 8192 + off * 16, bp + (tb + j) * 512 + off);
        }
        asm volatile("cp.async.commit_group;" ::: "memory");
    };

    float acc[2][8][4];
#pragma unroll
    for (int mtl = 0; mtl < 2; mtl++)
#pragma unroll
        for (int ntl = 0; ntl < 8; ntl++)
#pragma unroll
            for (int i = 0; i < 4; i++) acc[mtl][ntl][i] = 0.f;

    issue(0, 0);
    issue(1, 1);

    for (int j = 0; j < kT; j++) {
        if (j + 1 < kT) {
            asm volatile("cp.async.wait_group 1;" ::: "memory");
        } else {
            asm volatile("cp.async.wait_group 0;" ::: "memory");
        }
        __syncthreads();
        if (j + 2 < kT) issue(j + 2, (j + 2) % 3);

        const uint16_t* stg = smu + (j % 3) * STAGE_E;
#pragma unroll
        for (int kblk = 0; kblk < 2; kblk++) {
            uint4 ahi[2], alo[2];
#pragma unroll
            for (int mtl = 0; mtl < 2; mtl++) {
                const int mblk = wm * 2 + mtl;
                const int base = (mblk * 2 + kblk) * 256 + g * 32 + t4 * 8;
                ahi[mtl] = *(const uint4*)(stg + base);
                alo[mtl] = *(const uint4*)(stg + 4096 + base);
            }
#pragma unroll
            for (int ntl = 0; ntl < 8; ntl++) {
                const int nblk = wn * 8 + ntl;
                const int bbase = (nblk * 2 + kblk) * 128 + g * 16 + t4 * 4;
                uint2 bh = *(const uint2*)(stg + 8192 + bbase);
                uint2 bl = *(const uint2*)(stg + 12288 + bbase);
#pragma unroll
                for (int mtl = 0; mtl < 2; mtl++) {
                    mma_bf16(acc[mtl][ntl], (const uint32_t*)&ahi[mtl], (const uint32_t*)&bh);
                    mma_bf16(acc[mtl][ntl], (const uint32_t*)&ahi[mtl], (const uint32_t*)&bl);
                    mma_bf16(acc[mtl][ntl], (const uint32_t*)&alo[mtl], (const uint32_t*)&bh);
                }
            }
        }
    }

    const bool roundT = (nt >= roundFromTile);
    const int bm = mt * 128;
    const int bn = nt * 128;
#pragma unroll
    for (int mtl = 0; mtl < 2; mtl++) {
        const int r0 = bm + wm * 32 + mtl * 16 + g;
#pragma unroll
        for (int ntl = 0; ntl < 8; ntl++) {
            const int c0 = bn + wn * 64 + ntl * 8 + t4 * 2;
            const float b0 = bias[c0];
            const float b1 = bias[c0 + 1];
            float2 v0, v1;
            v0.x = acc[mtl][ntl][0] + b0; v0.y = acc[mtl][ntl][1] + b1;
            v1.x = acc[mtl][ntl][2] + b0; v1.y = acc[mtl][ntl][3] + b1;
            if (roundT) {
                v0.x = tf32_rna(v0.x); v0.y = tf32_rna(v0.y);
                v1.x = tf32_rna(v1.x); v1.y = tf32_rna(v1.y);
            }
            *(float2*)(C + (size_t)r0 * N + c0) = v0;
            *(float2*)(C + (size_t)(r0 + 8) * N + c0) = v1;
        }
    }
}

// ============================================================================
// Flash attention: tf32 mma.sync, producer-warp mbarrier pipeline.
// Block = 160 threads: warps 0-3 compute 32 q-rows each, warp 4 = producer.
// Each K/V byte now read by 4 warps instead of 8 -> smem bytes/tile -27%.
// ============================================================================
static constexpr int ABQ = 128, ABK = 32, APAD = 68, PPAD = 36;
static constexpr int QF0 = 32;
static constexpr int KV0 = QF0 + ABQ * APAD;            // 8736
static constexpr int PF0 = KV0 + 3 * 4352;              // 21792
static constexpr int ATTN_SMEM = (PF0 + 4 * 32 * PPAD) * 4;  // 105600 B

__global__ __launch_bounds__(160, 2) void attn_mma(
    const float* __restrict__ qkv, float* __restrict__ out)
{
    extern __shared__ float sm[];
    const int tid = threadIdx.x;
    const int wid = tid >> 5;
    const int lane = tid & 31;
    const int g = lane >> 2;
    const int t4 = lane & 3;
    const int qi = gridDim.x - 1 - blockIdx.x;
    const int h = blockIdx.y;
    const int b = blockIdx.z;
    const int q0 = qi * ABQ;
    const size_t rs = (size_t)3 * En;
    const float* qbase = qkv + (size_t)b * Sn * rs + (size_t)h * Dn;
    const float* kbase = qbase + En;
    const float* vbase = qbase + 2 * En;
    const uint32_t smem_base = (uint32_t)__cvta_generic_to_shared(sm);
    const int ntiles = 4 * qi + 4;

    if (tid == 0) {
#pragma unroll
        for (int s = 0; s < 3; s++) {
            MBARRIER_INIT(smem_base + s * 8, 32);        // full[s]: 32 producer lanes
            MBARRIER_INIT(smem_base + 24 + s * 8, 4);    // empty[s]: 4 compute warps
        }
    }

    // Q tile -> smem (scaled, rna-truncated); compute threads only
    if (tid < 128) {
        for (int i = tid; i < ABQ * 16; i += 128) {
            const int row = i >> 4, c4 = (i & 15) * 4;
            float4 v = *(const float4*)(qbase + (size_t)(q0 + row) * rs + c4);
            float4 hi;
            hi.x = tf32_rna(v.x * 0.125f);
            hi.y = tf32_rna(v.y * 0.125f);
            hi.z = tf32_rna(v.z * 0.125f);
            hi.w = tf32_rna(v.w * 0.125f);
            *(float4*)&sm[QF0 + row * APAD + c4] = hi;
        }
    }
    __syncthreads();   // mbarrier init + Q visible to all

    if (tid >= 128) {
        // -------- producer warp --------
        for (int j = 0; j < ntiles; j++) {
            const int q3 = j / 3;
            const int s = j - 3 * q3;
            if (j >= 3) {
                MBARRIER_WAIT_PARITY(smem_base + 24 + s * 8, (q3 - 1) & 1);
            }
            const int k0 = j * ABK;
            const int base = KV0 + s * 4352;
#pragma unroll
            for (int c = 0; c < 32; c++) {
                const int i = c * 32 + lane;
                const int isV = i >> 9;
                const int ii = i & 511;
                const int row = ii >> 4, q = ii & 15;
                const float* src = (isV ? vbase : kbase) + (size_t)(k0 + row) * rs + q * 4;
                const int dstf = base + isV * 2176 + row * APAD + q * 4;
                cp16(smem_base + dstf * 4, src);
            }
            asm volatile("cp.async.commit_group;" ::: "memory");
            if (j >= 2) {
                asm volatile("cp.async.wait_group 2;" ::: "memory");
                MBARRIER_ARRIVE(smem_base + ((j - 2) % 3) * 8);
            }
        }
        asm volatile("cp.async.wait_group 1;" ::: "memory");
        MBARRIER_ARRIVE(smem_base + ((ntiles - 2) % 3) * 8);
        asm volatile("cp.async.wait_group 0;" ::: "memory");
        MBARRIER_ARRIVE(smem_base + ((ntiles - 1) % 3) * 8);
        return;
    }

    // -------- compute warps: 32 q-rows each (mt = 2 blocks of 16) --------
    float m_[2][2], l_[2][2];
#pragma unroll
    for (int mt = 0; mt < 2; mt++) {
        m_[mt][0] = -1e30f; m_[mt][1] = -1e30f;
        l_[mt][0] = 0.f;    l_[mt][1] = 0.f;
    }
    float o[2][8][4];
#pragma unroll
    for (int mt = 0; mt < 2; mt++)
#pragma unroll
        for (int nt = 0; nt < 8; nt++)
#pragma unroll
            for (int i = 0; i < 4; i++) o[mt][nt][i] = 0.f;

    const int wrow = wid * 32;
    float* Pw = sm + PF0 + wid * (32 * PPAD);

    for (int jt = 0; jt < ntiles; jt++) {
        const int q3 = jt / 3;
        const int s = jt - 3 * q3;
        const int k0 = jt * ABK;
        MBARRIER_WAIT_PARITY(smem_base + s * 8, q3 & 1);

        const float* Kb = sm + KV0 + s * 4352;
        const float* Vb = Kb + 2176;

        // ---- S = (Q/8) @ K^T ----
        float acc[2][4][4];
#pragma unroll
        for (int mt = 0; mt < 2; mt++)
#pragma unroll
            for (int nt = 0; nt < 4; nt++)
#pragma unroll
                for (int i = 0; i < 4; i++) acc[mt][nt][i] = 0.f;

#pragma unroll
        for (int kb = 0; kb < 8; kb++) {
            uint32_t aq[2][4];
#pragma unroll
            for (int mt = 0; mt < 2; mt++) {
                const int r = wrow + mt * 16 + g;
                aq[mt][0] = __float_as_uint(sm[QF0 + r * APAD + kb * 8 + t4]);
                aq[mt][1] = __float_as_uint(sm[QF0 + (r + 8) * APAD + kb * 8 + t4]);
                aq[mt][2] = __float_as_uint(sm[QF0 + r * APAD + kb * 8 + t4 + 4]);
                aq[mt][3] = __float_as_uint(sm[QF0 + (r + 8) * APAD + kb * 8 + t4 + 4]);
            }
#pragma unroll
            for (int nt = 0; nt < 4; nt++) {
                uint32_t bh[2];
                bh[0] = __float_as_uint(Kb[(nt * 8 + g) * APAD + kb * 8 + t4]);
                bh[1] = __float_as_uint(Kb[(nt * 8 + g) * APAD + kb * 8 + t4 + 4]);
#pragma unroll
                for (int mt = 0; mt < 2; mt++)
                    mma_tf32(acc[mt][nt], aq[mt], bh);
            }
        }

        // ---- causal mask (4 diagonal-overlapping tiles) ----
        if (jt >= ntiles - 4) {
#pragma unroll
            for (int mt = 0; mt < 2; mt++) {
                const int r0g = q0 + wrow + mt * 16 + g;
                const int r1g = r0g + 8;
#pragma unroll
                for (int nt = 0; nt < 4; nt++) {
                    const int c = k0 + nt * 8 + t4 * 2;
                    if (c > r0g)     acc[mt][nt][0] = -1e30f;
                    if (c + 1 > r0g) acc[mt][nt][1] = -1e30f;
                    if (c > r1g)     acc[mt][nt][2] = -1e30f;
                    if (c + 1 > r1g) acc[mt][nt][3] = -1e30f;
                }
            }
        }

        // ---- online softmax (per mt block) ----
        float al[2][2];
#pragma unroll
        for (int mt = 0; mt < 2; mt++) {
            float mx0 = -1e30f, mx1 = -1e30f;
#pragma unroll
            for (int nt = 0; nt < 4; nt++) {
                mx0 = fmaxf(mx0, fmaxf(acc[mt][nt][0], acc[mt][nt][1]));
                mx1 = fmaxf(mx1, fmaxf(acc[mt][nt][2], acc[mt][nt][3]));
            }
            mx0 = fmaxf(mx0, __shfl_xor_sync(0xffffffffu, mx0, 1));
            mx0 = fmaxf(mx0, __shfl_xor_sync(0xffffffffu, mx0, 2));
            mx1 = fmaxf(mx1, __shfl_xor_sync(0xffffffffu, mx1, 1));
            mx1 = fmaxf(mx1, __shfl_xor_sync(0xffffffffu, mx1, 2));
            const float mn0 = fmaxf(m_[mt][0], mx0);
            const float mn1 = fmaxf(m_[mt][1], mx1);
            const float a0 = __expf(m_[mt][0] - mn0);
            const float a1 = __expf(m_[mt][1] - mn1);
            m_[mt][0] = mn0; m_[mt][1] = mn1;
            float s0 = 0.f, s1 = 0.f;
#pragma unroll
            for (int nt = 0; nt < 4; nt++) {
                acc[mt][nt][0] = __expf(acc[mt][nt][0] - mn0); s0 += acc[mt][nt][0];
                acc[mt][nt][1] = __expf(acc[mt][nt][1] - mn0); s0 += acc[mt][nt][1];
                acc[mt][nt][2] = __expf(acc[mt][nt][2] - mn1); s1 += acc[mt][nt][2];
                acc[mt][nt][3] = __expf(acc[mt][nt][3] - mn1); s1 += acc[mt][nt][3];
            }
            s0 += __shfl_xor_sync(0xffffffffu, s0, 1);
            s0 += __shfl_xor_sync(0xffffffffu, s0, 2);
            s1 += __shfl_xor_sync(0xffffffffu, s1, 1);
            s1 += __shfl_xor_sync(0xffffffffu, s1, 2);
            l_[mt][0] = l_[mt][0] * a0 + s0;
            l_[mt][1] = l_[mt][1] * a1 + s1;
            al[mt][0] = a0; al[mt][1] = a1;
        }

        // ---- P -> warp-private smem ----
#pragma unroll
        for (int mt = 0; mt < 2; mt++) {
            const int rb = mt * 16;
#pragma unroll
            for (int nt = 0; nt < 4; nt++) {
                Pw[(rb + g) * PPAD + nt * 8 + t4 * 2]           = tf32_rna(acc[mt][nt][0]);
                Pw[(rb + g) * PPAD + nt * 8 + t4 * 2 + 1]       = tf32_rna(acc[mt][nt][1]);
                Pw[(rb + g + 8) * PPAD + nt * 8 + t4 * 2]       = tf32_rna(acc[mt][nt][2]);
                Pw[(rb + g + 8) * PPAD + nt * 8 + t4 * 2 + 1]   = tf32_rna(acc[mt][nt][3]);
            }
        }
        __syncwarp();

        // ---- rescale O ----
#pragma unroll
        for (int mt = 0; mt < 2; mt++)
#pragma unroll
            for (int nt = 0; nt < 8; nt++) {
                o[mt][nt][0] *= al[mt][0]; o[mt][nt][1] *= al[mt][0];
                o[mt][nt][2] *= al[mt][1]; o[mt][nt][3] *= al[mt][1];
            }

        // ---- O += P @ V ----
#pragma unroll
        for (int kb = 0; kb < 4; kb++) {
            uint32_t ap[2][4];
#pragma unroll
            for (int mt = 0; mt < 2; mt++) {
                const int rb = mt * 16;
                ap[mt][0] = __float_as_uint(Pw[(rb + g) * PPAD + kb * 8 + t4]);
                ap[mt][1] = __float_as_uint(Pw[(rb + g + 8) * PPAD + kb * 8 + t4]);
                ap[mt][2] = __float_as_uint(Pw[(rb + g) * PPAD + kb * 8 + t4 + 4]);
                ap[mt][3] = __float_as_uint(Pw[(rb + g + 8) * PPAD + kb * 8 + t4 + 4]);
            }
#pragma unroll
            for (int nt = 0; nt < 8; nt++) {
                uint32_t bh[2];
                bh[0] = __float_as_uint(Vb[(kb * 8 + t4) * APAD + nt * 8 + g]);
                bh[1] = __float_as_uint(Vb[(kb * 8 + t4 + 4) * APAD + nt * 8 + g]);
#pragma unroll
                for (int mt = 0; mt < 2; mt++)
                    mma_tf32(o[mt][nt], ap[mt], bh);
            }
        }
        __syncwarp();
        if (lane == 0) MBARRIER_ARRIVE(smem_base + 24 + s * 8);
    }

    // ---- normalize + store ----
#pragma unroll
    for (int mt = 0; mt < 2; mt++) {
        const float i0 = 1.f / l_[mt][0];
        const float i1 = 1.f / l_[mt][1];
        const int r0g = q0 + wrow + mt * 16 + g;
#pragma unroll
        for (int nt = 0; nt < 8; nt++) {
            const int col = h * Dn + nt * 8 + t4 * 2;
            float2 v0, v1;
            v0.x = o[mt][nt][0] * i0; v0.y = o[mt][nt][1] * i0;
            v1.x = o[mt][nt][2] * i1; v1.y = o[mt][nt][3] * i1;
            *(float2*)(out + ((size_t)b * Sn + r0g) * En + col) = v0;
            *(float2*)(out + ((size_t)b * Sn + r0g + 8) * En + col) = v1;
        }
    }
}

// ----------------------------------------------------------------------------
extern "C" void kernel_launch(void* const* d_in, const int* in_sizes, int n_in,
                              void* d_out, int out_size)
{
    const float* x     = (const float*)d_in[0];
    const float* w_in  = (const float*)d_in[1];
    const float* b_in  = (const float*)d_in[2];
    const float* w_out = (const float*)d_in[3];
    const float* b_out = (const float*)d_in[4];
    float* out = (float*)d_out;

    float *qkv, *attn;
    uint4 *xh, *xl, *ah, *al, *wih, *wil, *woh, *wol;
    cudaGetSymbolAddress((void**)&qkv, g_qkv);
    cudaGetSymbolAddress((void**)&attn, g_attn);
    cudaGetSymbolAddress((void**)&xh, g_xh);
    cudaGetSymbolAddress((void**)&xl, g_xl);
    cudaGetSymbolAddress((void**)&ah, g_ah);
    cudaGetSymbolAddress((void**)&al, g_al);
    cudaGetSymbolAddress((void**)&wih, g_wih);
    cudaGetSymbolAddress((void**)&wil, g_wil);
    cudaGetSymbolAddress((void**)&woh, g_woh);
    cudaGetSymbolAddress((void**)&wol, g_wol);

    static bool attr_set = false;
    if (!attr_set) {
        cudaFuncSetAttribute(gemm_pre, cudaFuncAttributeMaxDynamicSharedMemorySize,
                             GEMM_SMEM);
        cudaFuncSetAttribute(attn_mma, cudaFuncAttributeMaxDynamicSharedMemorySize,
                             ATTN_SMEM);
        attr_set = true;
    }

    // 0) Pre-split operands into fragment-major bf16 hi/lo
    prep_a<<<4096, 256>>>(x, xh, xl, En);
    prep_b<<<1536, 256>>>(w_in, wih, wil, En);

    // 1) QKV projection; K/V columns (tiles >= 8) pre-rounded to tf32
    {
        dim3 grid(24, 64);
        gemm_pre<<<grid, 256, GEMM_SMEM>>>(xh, xl, wih, wil, b_in, qkv,
                                           3 * En, En / 32, 8);
    }

    // 2) Causal flash attention (tf32, 4 fat compute warps + producer)
    {
        dim3 grid(Sn / ABQ, Hn, Bn);
        attn_mma<<<grid, 160, ATTN_SMEM>>>(qkv, attn);
    }

    // 3) Output projection
    prep_a<<<4096, 256>>>(attn, ah, al, En);
    prep_b<<<512, 256>>>(w_out, woh, wol, En);
    {
        dim3 grid(8, 64);
        gemm_pre<<<grid, 256, GEMM_SMEM>>>(ah, al, woh, wol, b_out, out,
                                           En, En / 32, 1 << 30);
    }
}